// round 6
// baseline (speedup 1.0000x reference)
#include <cuda_runtime.h>
#include <cuda_bf16.h>
#include <cstdint>

// ---------------- problem constants ----------------
#define N_EMBD 1024
#define N_HEAD 16
#define DKH    64
#define BB     2
#define TT     2048
#define BT     (BB*TT)     // 4096 rows
#define C3     (3*N_EMBD)  // 3072

// scratch (allocation-free: device globals)
__device__ float g_qkv[BT * C3];      // [4096][3072]
__device__ float g_att[BT * N_EMBD];  // [4096][1024]

// ---------------- bf16 helpers ----------------
__device__ __forceinline__ uint32_t packbf(__nv_bfloat16 a, __nv_bfloat16 b) {
    return (uint32_t)__bfloat16_as_ushort(a) | ((uint32_t)__bfloat16_as_ushort(b) << 16);
}

__device__ __forceinline__ void split2(float f0, float f1, uint32_t& hi, uint32_t& lo) {
    __nv_bfloat16 h0 = __float2bfloat16_rn(f0);
    __nv_bfloat16 h1 = __float2bfloat16_rn(f1);
    float r0 = f0 - __bfloat162float(h0);
    float r1 = f1 - __bfloat162float(h1);
    hi = packbf(h0, h1);
    lo = packbf(__float2bfloat16_rn(r0), __float2bfloat16_rn(r1));
}

__device__ __forceinline__ void mma_bf16(float d[4], const uint32_t a[4], const uint32_t b[2]) {
    asm volatile(
        "mma.sync.aligned.m16n8k16.row.col.f32.bf16.bf16.f32 "
        "{%0,%1,%2,%3}, {%4,%5,%6,%7}, {%8,%9}, {%0,%1,%2,%3};\n"
        : "+f"(d[0]), "+f"(d[1]), "+f"(d[2]), "+f"(d[3])
        : "r"(a[0]), "r"(a[1]), "r"(a[2]), "r"(a[3]),
          "r"(b[0]), "r"(b[1]));
}

__device__ __forceinline__ void ldsm_x4(uint32_t d[4], uint32_t addr) {
    asm volatile("ldmatrix.sync.aligned.m8n8.x4.shared.b16 {%0,%1,%2,%3}, [%4];"
                 : "=r"(d[0]), "=r"(d[1]), "=r"(d[2]), "=r"(d[3]) : "r"(addr));
}

__device__ __forceinline__ void ldm_x2_t(uint32_t& r0, uint32_t& r1, uint32_t addr) {
    asm volatile("ldmatrix.sync.aligned.m8n8.x2.trans.shared.b16 {%0,%1}, [%2];"
                 : "=r"(r0), "=r"(r1) : "r"(addr));
}

__device__ __forceinline__ uint32_t smem_u32(const void* p) {
    return (uint32_t)__cvta_generic_to_shared(p);
}

// ---------------- NT GEMM (ldmatrix + double-buffer, 3-term bf16 split) ----------------
// C[M,N] = A[M,K]*B[N,K]^T. Block 128x128x32; warp tile 64x32 (2x4 warp grid).
// SMEM buffer (bf16 elems, row stride 40): Ah@0, Al@5120, Bh@10240, Bl@15360 (20480/buf)
#define QBM 128
#define QBN 128
#define QBK 32
#define GEMM_SMEM (2 * 40960)

__global__ __launch_bounds__(256) void gemm_nt_ldsm(const float* __restrict__ A,
                                                    const float* __restrict__ Bm,
                                                    float* __restrict__ Cm,
                                                    int M, int N, int K)
{
    extern __shared__ __nv_bfloat16 sb[];
    const int tid = threadIdx.x, wid = tid >> 5, lane = tid & 31;
    const int wm = wid >> 2;          // 0..1
    const int wn = wid & 3;           // 0..3
    const int r = lane >> 2, tg = lane & 3;
    const int m0 = blockIdx.y * QBM, n0 = blockIdx.x * QBN;
    const uint32_t sbase = smem_u32(sb);

    const int srow = tid >> 1;            // 0..127
    const int shalf = (tid & 1) * 16;     // 0 / 16

    const float* Ap = A + (size_t)(m0 + srow) * K + shalf;
    const float* Bp = Bm + (size_t)(n0 + srow) * K + shalf;

    float acc[4][4][4] = {};
    float ra[16], rb[16];

    // prologue: load + stage block 0
#pragma unroll
    for (int q = 0; q < 4; q++) {
        *reinterpret_cast<float4*>(ra + q * 4) = *reinterpret_cast<const float4*>(Ap + q * 4);
        *reinterpret_cast<float4*>(rb + q * 4) = *reinterpret_cast<const float4*>(Bp + q * 4);
    }
#pragma unroll
    for (int q = 0; q < 4; q++) {
        uint32_t h0, l0, h1, l1;
        int col = srow * 40 + shalf + q * 4;
        split2(ra[q*4+0], ra[q*4+1], h0, l0);
        split2(ra[q*4+2], ra[q*4+3], h1, l1);
        *reinterpret_cast<uint2*>(&sb[col])        = make_uint2(h0, h1);
        *reinterpret_cast<uint2*>(&sb[5120 + col]) = make_uint2(l0, l1);
        split2(rb[q*4+0], rb[q*4+1], h0, l0);
        split2(rb[q*4+2], rb[q*4+3], h1, l1);
        *reinterpret_cast<uint2*>(&sb[10240 + col]) = make_uint2(h0, h1);
        *reinterpret_cast<uint2*>(&sb[15360 + col]) = make_uint2(l0, l1);
    }
    __syncthreads();

    const int nblk = K / QBK;
    const int arow_off = (lane & 7) + ((lane >> 3) & 1) * 8;
    const int acol_off = ((lane >> 4) & 1) * 8;
    const int brow_off = ((lane >> 4) & 1) * 8 + (lane & 7);
    const int bcol_off = ((lane >> 3) & 1) * 8;

    for (int i = 0; i < nblk; i++) {
        if (i + 1 < nblk) {
#pragma unroll
            for (int q = 0; q < 4; q++) {
                *reinterpret_cast<float4*>(ra + q * 4) =
                    *reinterpret_cast<const float4*>(Ap + (i + 1) * QBK + q * 4);
                *reinterpret_cast<float4*>(rb + q * 4) =
                    *reinterpret_cast<const float4*>(Bp + (i + 1) * QBK + q * 4);
            }
        }
        const uint32_t abase = sbase + (uint32_t)(i & 1) * 40960u;
#pragma unroll
        for (int s = 0; s < 2; s++) {
            const int ks = s * 16;
            uint32_t af_h[4][4], af_l[4][4];
#pragma unroll
            for (int ti = 0; ti < 4; ti++) {
                int arow = wm * 64 + ti * 16 + arow_off;
                uint32_t ad = abase + (uint32_t)(arow * 40 + ks + acol_off) * 2u;
                ldsm_x4(af_h[ti], ad);
                ldsm_x4(af_l[ti], ad + 10240u);
            }
            uint32_t bf_h[4][2], bf_l[4][2];
#pragma unroll
            for (int g = 0; g < 2; g++) {
                int brow = wn * 32 + g * 16 + brow_off;
                uint32_t bd = abase + 20480u + (uint32_t)(brow * 40 + ks + bcol_off) * 2u;
                uint32_t d[4];
                ldsm_x4(d, bd);
                bf_h[2*g][0] = d[0]; bf_h[2*g][1] = d[1];
                bf_h[2*g+1][0] = d[2]; bf_h[2*g+1][1] = d[3];
                ldsm_x4(d, bd + 10240u);
                bf_l[2*g][0] = d[0]; bf_l[2*g][1] = d[1];
                bf_l[2*g+1][0] = d[2]; bf_l[2*g+1][1] = d[3];
            }
#pragma unroll
            for (int ti = 0; ti < 4; ti++)
#pragma unroll
                for (int j = 0; j < 4; j++) {
                    mma_bf16(acc[ti][j], af_h[ti], bf_h[j]);
                    mma_bf16(acc[ti][j], af_l[ti], bf_h[j]);
                    mma_bf16(acc[ti][j], af_h[ti], bf_l[j]);
                }
        }
        if (i + 1 < nblk) {
            __nv_bfloat16* nb = sb + ((i + 1) & 1) * 20480;
#pragma unroll
            for (int q = 0; q < 4; q++) {
                uint32_t h0, l0, h1, l1;
                int col = srow * 40 + shalf + q * 4;
                split2(ra[q*4+0], ra[q*4+1], h0, l0);
                split2(ra[q*4+2], ra[q*4+3], h1, l1);
                *reinterpret_cast<uint2*>(nb + col)        = make_uint2(h0, h1);
                *reinterpret_cast<uint2*>(nb + 5120 + col) = make_uint2(l0, l1);
                split2(rb[q*4+0], rb[q*4+1], h0, l0);
                split2(rb[q*4+2], rb[q*4+3], h1, l1);
                *reinterpret_cast<uint2*>(nb + 10240 + col) = make_uint2(h0, h1);
                *reinterpret_cast<uint2*>(nb + 15360 + col) = make_uint2(l0, l1);
            }
            __syncthreads();
        }
    }

#pragma unroll
    for (int ti = 0; ti < 4; ti++) {
        size_t row0 = (size_t)(m0 + wm * 64 + ti * 16 + r);
#pragma unroll
        for (int j = 0; j < 4; j++) {
            int col = n0 + wn * 32 + j * 8 + 2 * tg;
            *reinterpret_cast<float2*>(Cm + row0 * N + col) =
                make_float2(acc[ti][j][0], acc[ti][j][1]);
            *reinterpret_cast<float2*>(Cm + (row0 + 8) * N + col) =
                make_float2(acc[ti][j][2], acc[ti][j][3]);
        }
    }
}

// ---------------- causal flash attention v2 ----------------
// q-tile 128 (one warp = 16 rows, full 64-col span), kv-tile 64.
// Warp-local softmax; Q fragments in registers; P never leaves registers.
__global__ __launch_bounds__(256) void attn_v2(const float* __restrict__ qkv,
                                               float* __restrict__ att)
{
    __shared__ uint32_t Kh[64][36], Kl[64][36];          // [n][k-pairs]
    __shared__ __nv_bfloat16 Vh[64][72], Vl[64][72];     // [kv][dk]

    const int tid = threadIdx.x, wid = tid >> 5, lane = tid & 31;
    const int r = lane >> 2, tg = lane & 3;
    const int qt = (int)gridDim.x - 1 - (int)blockIdx.x;   // descending size
    const int bh_ = blockIdx.y;
    const int b = bh_ >> 4, h = bh_ & 15;

    const uint32_t kh_base = smem_u32(&Kh[0][0]);
    const uint32_t kl_base = smem_u32(&Kl[0][0]);
    const uint32_t vh_base = smem_u32(&Vh[0][0]);
    const uint32_t vl_base = smem_u32(&Vl[0][0]);

    // Q fragments (4 k16 groups), loaded once, pre-scaled by 0.125
    uint32_t qh[4][4], ql[4][4];
    {
        const float* Qp = qkv + (size_t)(b * TT + qt * 128 + wid * 16) * C3 + h * DKH;
#pragma unroll
        for (int s = 0; s < 4; s++)
#pragma unroll
            for (int hk = 0; hk < 2; hk++) {
                int col = s * 16 + hk * 8 + 2 * tg;
                float2 v0 = *reinterpret_cast<const float2*>(Qp + (size_t)r * C3 + col);
                float2 v1 = *reinterpret_cast<const float2*>(Qp + (size_t)(r + 8) * C3 + col);
                split2(v0.x * 0.125f, v0.y * 0.125f, qh[s][hk * 2 + 0], ql[s][hk * 2 + 0]);
                split2(v1.x * 0.125f, v1.y * 0.125f, qh[s][hk * 2 + 1], ql[s][hk * 2 + 1]);
            }
    }

    float oacc[8][4] = {};
    float m0_ = -1e30f, m1_ = -1e30f, l0_ = 0.f, l1_ = 0.f;
    const int wrow_lo = qt * 128 + wid * 16;
    const int ktmax = qt * 2 + 1;

    const int krow_off = ((lane >> 4) & 1) * 8 + (lane & 7);
    const int kcol_bit = ((lane >> 3) & 1) * 8;

    for (int kt = 0; kt <= ktmax; kt++) {
        __syncthreads();   // prior PV reads of K/V done
        // stage + split K,V (64 rows)
#pragma unroll
        for (int it = 0; it < 4; it++) {
            int l = tid + it * 256;
            int row = l >> 4, c4 = l & 15;
            size_t base = (size_t)(b * TT + kt * 64 + row) * C3 + h * DKH + c4 * 4;
            float4 kv = *reinterpret_cast<const float4*>(qkv + base + N_EMBD);
            float4 vv = *reinterpret_cast<const float4*>(qkv + base + 2 * N_EMBD);
            split2(kv.x, kv.y, Kh[row][c4 * 2],     Kl[row][c4 * 2]);
            split2(kv.z, kv.w, Kh[row][c4 * 2 + 1], Kl[row][c4 * 2 + 1]);
            uint32_t h01, l01, h23, l23;
            split2(vv.x, vv.y, h01, l01);
            split2(vv.z, vv.w, h23, l23);
            uint32_t* vh32 = reinterpret_cast<uint32_t*>(&Vh[row][c4 * 4]);
            uint32_t* vl32 = reinterpret_cast<uint32_t*>(&Vl[row][c4 * 4]);
            vh32[0] = h01; vh32[1] = h23;
            vl32[0] = l01; vl32[1] = l23;
        }
        __syncthreads();

        if (wrow_lo + 15 < kt * 64) continue;   // warp fully above diagonal

        // ---- S = Q K^T ----
        float sacc[8][4] = {};
#pragma unroll
        for (int s = 0; s < 4; s++) {
            const uint32_t bcolb = (uint32_t)(s * 16 + kcol_bit) * 2u;
#pragma unroll
            for (int g = 0; g < 4; g++) {
                uint32_t brow = (uint32_t)(g * 16 + krow_off);
                uint32_t dh[4], dl[4];
                ldsm_x4(dh, kh_base + brow * 144u + bcolb);
                ldsm_x4(dl, kl_base + brow * 144u + bcolb);
                uint32_t b0[2] = { dh[0], dh[1] }, b1[2] = { dh[2], dh[3] };
                uint32_t c0[2] = { dl[0], dl[1] }, c1[2] = { dl[2], dl[3] };
                mma_bf16(sacc[2*g],     qh[s], b0);
                mma_bf16(sacc[2*g],     ql[s], b0);
                mma_bf16(sacc[2*g],     qh[s], c0);
                mma_bf16(sacc[2*g + 1], qh[s], b1);
                mma_bf16(sacc[2*g + 1], ql[s], b1);
                mma_bf16(sacc[2*g + 1], qh[s], c1);
            }
        }

        // ---- mask + warp-local softmax ----
        const int mg0 = wrow_lo + r;
        float mx0 = -1e30f, mx1 = -1e30f;
#pragma unroll
        for (int j = 0; j < 8; j++) {
            int ng = kt * 64 + j * 8 + 2 * tg;
            if (ng     > mg0)     sacc[j][0] = -1e30f;
            if (ng + 1 > mg0)     sacc[j][1] = -1e30f;
            if (ng     > mg0 + 8) sacc[j][2] = -1e30f;
            if (ng + 1 > mg0 + 8) sacc[j][3] = -1e30f;
            mx0 = fmaxf(mx0, fmaxf(sacc[j][0], sacc[j][1]));
            mx1 = fmaxf(mx1, fmaxf(sacc[j][2], sacc[j][3]));
        }
        mx0 = fmaxf(mx0, __shfl_xor_sync(0xffffffffu, mx0, 1));
        mx0 = fmaxf(mx0, __shfl_xor_sync(0xffffffffu, mx0, 2));
        mx1 = fmaxf(mx1, __shfl_xor_sync(0xffffffffu, mx1, 1));
        mx1 = fmaxf(mx1, __shfl_xor_sync(0xffffffffu, mx1, 2));
        float mn0 = fmaxf(m0_, mx0), mn1 = fmaxf(m1_, mx1);
        float cr0 = __expf(m0_ - mn0), cr1 = __expf(m1_ - mn1);
        m0_ = mn0; m1_ = mn1;
        float s0 = 0.f, s1 = 0.f;
#pragma unroll
        for (int j = 0; j < 8; j++) {
            sacc[j][0] = __expf(sacc[j][0] - mn0);
            sacc[j][1] = __expf(sacc[j][1] - mn0);
            sacc[j][2] = __expf(sacc[j][2] - mn1);
            sacc[j][3] = __expf(sacc[j][3] - mn1);
            s0 += sacc[j][0] + sacc[j][1];
            s1 += sacc[j][2] + sacc[j][3];
        }
        s0 += __shfl_xor_sync(0xffffffffu, s0, 1);
        s0 += __shfl_xor_sync(0xffffffffu, s0, 2);
        s1 += __shfl_xor_sync(0xffffffffu, s1, 1);
        s1 += __shfl_xor_sync(0xffffffffu, s1, 2);
        l0_ = l0_ * cr0 + s0;
        l1_ = l1_ * cr1 + s1;
#pragma unroll
        for (int j = 0; j < 8; j++) {
            oacc[j][0] *= cr0; oacc[j][1] *= cr0;
            oacc[j][2] *= cr1; oacc[j][3] *= cr1;
        }

        // ---- O += P V  (P straight from registers: C-frag == A-frag layout) ----
#pragma unroll
        for (int g = 0; g < 4; g++) {
            uint32_t pah[4], pal[4];
            split2(sacc[2*g][0],     sacc[2*g][1],     pah[0], pal[0]);
            split2(sacc[2*g][2],     sacc[2*g][3],     pah[1], pal[1]);
            split2(sacc[2*g + 1][0], sacc[2*g + 1][1], pah[2], pal[2]);
            split2(sacc[2*g + 1][2], sacc[2*g + 1][3], pah[3], pal[3]);
            uint32_t krow = (uint32_t)(g * 16 + (lane & 15));
#pragma unroll
            for (int j = 0; j < 8; j++) {
                uint32_t vh0, vh1, vl0, vl1;
                ldm_x2_t(vh0, vh1, vh_base + krow * 144u + (uint32_t)j * 16u);
                ldm_x2_t(vl0, vl1, vl_base + krow * 144u + (uint32_t)j * 16u);
                uint32_t bhf[2] = { vh0, vh1 }, blf[2] = { vl0, vl1 };
                mma_bf16(oacc[j], pah, bhf);
                mma_bf16(oacc[j], pal, bhf);
                mma_bf16(oacc[j], pah, blf);
            }
        }
    }

    // epilogue
    {
        float inv0 = 1.f / l0_, inv1 = 1.f / l1_;
        size_t row0 = (size_t)(b * TT + qt * 128 + wid * 16 + r);
#pragma unroll
        for (int j = 0; j < 8; j++) {
            int col = h * DKH + j * 8 + 2 * tg;
            *reinterpret_cast<float2*>(att + row0 * N_EMBD + col) =
                make_float2(oacc[j][0] * inv0, oacc[j][1] * inv0);
            *reinterpret_cast<float2*>(att + (row0 + 8) * N_EMBD + col) =
                make_float2(oacc[j][2] * inv1, oacc[j][3] * inv1);
        }
    }
}

// ---------------- launch ----------------
extern "C" void kernel_launch(void* const* d_in, const int* in_sizes, int n_in,
                              void* d_out, int out_size)
{
    const float* x  = (const float*)d_in[0];   // [2,2048,1024]
    const float* wa = (const float*)d_in[1];   // [3072,1024]
    const float* wp = (const float*)d_in[2];   // [1024,1024]
    float* out = (float*)d_out;                // [2,2048,1024]

    float* qkv_ptr = nullptr;
    float* att_ptr = nullptr;
    cudaGetSymbolAddress((void**)&qkv_ptr, g_qkv);
    cudaGetSymbolAddress((void**)&att_ptr, g_att);

    cudaFuncSetAttribute(gemm_nt_ldsm,
                         cudaFuncAttributeMaxDynamicSharedMemorySize, GEMM_SMEM);

    // 1) fused QKV projection: [4096,3072]
    gemm_nt_ldsm<<<dim3(C3 / QBN, BT / QBM), 256, GEMM_SMEM>>>(x, wa, qkv_ptr, BT, C3, N_EMBD);

    // 2) causal attention (q-tile 128)
    attn_v2<<<dim3(TT / 128, BB * N_HEAD), 256>>>(qkv_ptr, att_ptr);

    // 3) output projection: [4096,1024]
    gemm_nt_ldsm<<<dim3(N_EMBD / QBN, BT / QBM), 256, GEMM_SMEM>>>(att_ptr, wp, out, BT, N_EMBD, N_EMBD);
}

// round 7
// speedup vs baseline: 1.2370x; 1.2370x over previous
#include <cuda_runtime.h>
#include <cuda_fp16.h>
#include <cstdint>

// ---------------- problem constants ----------------
#define N_EMBD 1024
#define N_HEAD 16
#define DKH    64
#define BB     2
#define TT     2048
#define BT     (BB*TT)     // 4096 rows
#define C3     (3*N_EMBD)  // 3072

// scratch (allocation-free: device globals)
__device__ float g_qkv[BT * C3];      // [4096][3072]
__device__ float g_att[BT * N_EMBD];  // [4096][1024]

// ---------------- fp16 helpers ----------------
__device__ __forceinline__ uint32_t packh2(__half a, __half b) {
    return (uint32_t)__half_as_ushort(a) | ((uint32_t)__half_as_ushort(b) << 16);
}

// split two fp32 into fp16 hi pair + fp16 residual-lo pair
__device__ __forceinline__ void split2h(float f0, float f1, uint32_t& hi, uint32_t& lo) {
    __half h0 = __float2half_rn(f0);
    __half h1 = __float2half_rn(f1);
    float r0 = f0 - __half2float(h0);
    float r1 = f1 - __half2float(h1);
    hi = packh2(h0, h1);
    lo = packh2(__float2half_rn(r0), __float2half_rn(r1));
}

// round two fp32 to a single packed fp16 pair
__device__ __forceinline__ uint32_t round2h(float f0, float f1) {
    return packh2(__float2half_rn(f0), __float2half_rn(f1));
}

__device__ __forceinline__ void mma_fp16(float d[4], const uint32_t a[4], const uint32_t b[2]) {
    asm volatile(
        "mma.sync.aligned.m16n8k16.row.col.f32.f16.f16.f32 "
        "{%0,%1,%2,%3}, {%4,%5,%6,%7}, {%8,%9}, {%0,%1,%2,%3};\n"
        : "+f"(d[0]), "+f"(d[1]), "+f"(d[2]), "+f"(d[3])
        : "r"(a[0]), "r"(a[1]), "r"(a[2]), "r"(a[3]),
          "r"(b[0]), "r"(b[1]));
}

__device__ __forceinline__ void ldm_x2_t(uint32_t& r0, uint32_t& r1, uint32_t addr) {
    asm volatile("ldmatrix.sync.aligned.m8n8.x2.trans.shared.b16 {%0,%1}, [%2];"
                 : "=r"(r0), "=r"(r1) : "r"(addr));
}

// ---------------- NT GEMM (fp16 2-term: A split hi/lo, B rounded) ----------------
// C[M,N] = A[M,K] * B[N,K]^T ; A,B,C row-major fp32.
#define GBM 128
#define GBN 64
#define GBK 32
#define GKP 20   // GBK/2 + 4 pad (u32 per row)

__global__ __launch_bounds__(256) void gemm_nt_h2(const float* __restrict__ A,
                                                  const float* __restrict__ Bm,
                                                  float* __restrict__ Cm,
                                                  int M, int N, int K)
{
    __shared__ uint32_t Ah[GBM][GKP], Al[GBM][GKP];
    __shared__ uint32_t Bh[GBN][GKP];

    const int tid  = threadIdx.x;
    const int wid  = tid >> 5, lane = tid & 31;
    const int wm   = wid & 3,  wn   = wid >> 2;   // 4x2 warp grid, warp tile 32x32
    const int r    = lane >> 2, tg  = lane & 3;
    const int m0   = blockIdx.y * GBM;
    const int n0   = blockIdx.x * GBN;

    float acc[2][4][4] = {};

    for (int kt = 0; kt < K; kt += GBK) {
        // stage+split A tile: 128x32 floats
#pragma unroll
        for (int it = 0; it < 4; it++) {
            int l = tid + it * 256;
            int row = l >> 3, c4 = l & 7;
            float4 v = *reinterpret_cast<const float4*>(
                A + (size_t)(m0 + row) * K + kt + c4 * 4);
            split2h(v.x, v.y, Ah[row][c4 * 2],     Al[row][c4 * 2]);
            split2h(v.z, v.w, Ah[row][c4 * 2 + 1], Al[row][c4 * 2 + 1]);
        }
        // stage B tile rounded to fp16: 64x32 floats
#pragma unroll
        for (int it = 0; it < 2; it++) {
            int l = tid + it * 256;
            int row = l >> 3, c4 = l & 7;
            float4 v = *reinterpret_cast<const float4*>(
                Bm + (size_t)(n0 + row) * K + kt + c4 * 4);
            Bh[row][c4 * 2]     = round2h(v.x, v.y);
            Bh[row][c4 * 2 + 1] = round2h(v.z, v.w);
        }
        __syncthreads();

#pragma unroll
        for (int kb = 0; kb < GBK / 2; kb += 8) {   // kb = k16 step in u32 units
            uint32_t ah[2][4], al[2][4];
#pragma unroll
            for (int i = 0; i < 2; i++) {
                int mr = wm * 32 + i * 16 + r;
                ah[i][0] = Ah[mr][kb + tg];         al[i][0] = Al[mr][kb + tg];
                ah[i][1] = Ah[mr + 8][kb + tg];     al[i][1] = Al[mr + 8][kb + tg];
                ah[i][2] = Ah[mr][kb + tg + 4];     al[i][2] = Al[mr][kb + tg + 4];
                ah[i][3] = Ah[mr + 8][kb + tg + 4]; al[i][3] = Al[mr + 8][kb + tg + 4];
            }
#pragma unroll
            for (int j = 0; j < 4; j++) {
                int nr = wn * 32 + j * 8 + r;
                uint32_t bhf[2] = { Bh[nr][kb + tg], Bh[nr][kb + tg + 4] };
#pragma unroll
                for (int i = 0; i < 2; i++) {
                    mma_fp16(acc[i][j], ah[i], bhf);
                    mma_fp16(acc[i][j], al[i], bhf);
                }
            }
        }
        __syncthreads();
    }

#pragma unroll
    for (int i = 0; i < 2; i++) {
        size_t row0 = (size_t)(m0 + wm * 32 + i * 16 + r);
#pragma unroll
        for (int j = 0; j < 4; j++) {
            int col = n0 + wn * 32 + j * 8 + 2 * tg;
            *reinterpret_cast<float2*>(Cm + row0 * N + col) =
                make_float2(acc[i][j][0], acc[i][j][1]);
            *reinterpret_cast<float2*>(Cm + (row0 + 8) * N + col) =
                make_float2(acc[i][j][2], acc[i][j][3]);
        }
    }
}

// ---------------- causal flash attention (fp16 2-term, reg softmax) ----------------
// smem layout (bytes):
//   Qh 0, Ql 9216, Kh 18432, Vh 27648, Vl 36864, Ph 46080,
//   pmax 55296 (2*64 f32), psum 55808 (2*64 f32)  -> total 56320
#define ATT_SMEM_BYTES 56320

__global__ __launch_bounds__(256) void attn_h2(const float* __restrict__ qkv,
                                               float* __restrict__ att)
{
    extern __shared__ char smc[];
    uint32_t (*Qh)[36] = (uint32_t(*)[36])(smc);
    uint32_t (*Ql)[36] = (uint32_t(*)[36])(smc + 9216);
    uint32_t (*Kh)[36] = (uint32_t(*)[36])(smc + 18432);
    __half (*Vh)[72] = (__half(*)[72])(smc + 27648);
    __half (*Vl)[72] = (__half(*)[72])(smc + 36864);
    uint32_t (*Ph)[36] = (uint32_t(*)[36])(smc + 46080);
    float* pmax = (float*)(smc + 55296);   // [2][64]
    float* psum = (float*)(smc + 55808);   // [2][64]

    const int tid  = threadIdx.x;
    const int wid  = tid >> 5, lane = tid & 31;
    const int wm   = wid & 3,  wn   = wid >> 2;   // warp S-tile rows wm*16..+16, cols wn*32..+32
    const int r    = lane >> 2, tg  = lane & 3;
    const int qt   = (int)gridDim.x - 1 - (int)blockIdx.x;   // big tiles first
    const int bh_  = blockIdx.y;
    const int b    = bh_ >> 4, h = bh_ & 15;

    const uint32_t vh_base = (uint32_t)__cvta_generic_to_shared(Vh);
    const uint32_t vl_base = (uint32_t)__cvta_generic_to_shared(Vl);

    // stage Q (pre-scaled by DK^-0.5 = 0.125), split to fp16 hi/lo pairs along k
#pragma unroll
    for (int it = 0; it < 4; it++) {
        int l = tid + it * 256;
        int row = l >> 4, c4 = l & 15;
        float4 v = *reinterpret_cast<const float4*>(
            qkv + (size_t)(b * TT + qt * 64 + row) * C3 + h * DKH + c4 * 4);
        split2h(v.x * 0.125f, v.y * 0.125f, Qh[row][c4 * 2],     Ql[row][c4 * 2]);
        split2h(v.z * 0.125f, v.w * 0.125f, Qh[row][c4 * 2 + 1], Ql[row][c4 * 2 + 1]);
    }

    const int mr  = wm * 16 + r;          // local row (0..63), second row mr+8
    float m0_ = -1e30f, m1_ = -1e30f;     // per-row running max (registers)
    float l0_ = 0.f,    l1_ = 0.f;        // per-row running sum (registers)
    float oacc[4][4] = {};

    for (int kt = 0; kt <= qt; kt++) {
        __syncthreads();   // S0: Q staged (first iter) / prev PV reads of K,V,P done

        // stage K (rounded fp16) + V (split) tiles
#pragma unroll
        for (int it = 0; it < 4; it++) {
            int l = tid + it * 256;
            int row = l >> 4, c4 = l & 15;
            size_t base = (size_t)(b * TT + kt * 64 + row) * C3 + h * DKH + c4 * 4;
            float4 kv = *reinterpret_cast<const float4*>(qkv + base + N_EMBD);
            float4 vv = *reinterpret_cast<const float4*>(qkv + base + 2 * N_EMBD);
            Kh[row][c4 * 2]     = round2h(kv.x, kv.y);
            Kh[row][c4 * 2 + 1] = round2h(kv.z, kv.w);
            uint32_t h01, l01, h23, l23;
            split2h(vv.x, vv.y, h01, l01);
            split2h(vv.z, vv.w, h23, l23);
            uint32_t* vh32 = reinterpret_cast<uint32_t*>(&Vh[row][c4 * 4]);
            uint32_t* vl32 = reinterpret_cast<uint32_t*>(&Vl[row][c4 * 4]);
            vh32[0] = h01; vh32[1] = h23;
            vl32[0] = l01; vl32[1] = l23;
        }
        __syncthreads();   // S1

        // S = Q K^T  (Q split 2-term, K single fp16)
        float sacc[4][4] = {};
#pragma unroll
        for (int kb = 0; kb < 32; kb += 8) {
            uint32_t ah[4], al[4];
            ah[0] = Qh[mr][kb + tg];         al[0] = Ql[mr][kb + tg];
            ah[1] = Qh[mr + 8][kb + tg];     al[1] = Ql[mr + 8][kb + tg];
            ah[2] = Qh[mr][kb + tg + 4];     al[2] = Ql[mr][kb + tg + 4];
            ah[3] = Qh[mr + 8][kb + tg + 4]; al[3] = Ql[mr + 8][kb + tg + 4];
#pragma unroll
            for (int j = 0; j < 4; j++) {
                int nr = wn * 32 + j * 8 + r;
                uint32_t bhf[2] = { Kh[nr][kb + tg], Kh[nr][kb + tg + 4] };
                mma_fp16(sacc[j], ah, bhf);
                mma_fp16(sacc[j], al, bhf);
            }
        }

        // mask + per-row max (warp partial)
        const int mg0 = qt * 64 + mr;
        float mx0 = -1e30f, mx1 = -1e30f;
#pragma unroll
        for (int j = 0; j < 4; j++) {
            int ng = kt * 64 + wn * 32 + j * 8 + 2 * tg;
            if (ng     > mg0)     sacc[j][0] = -1e30f;
            if (ng + 1 > mg0)     sacc[j][1] = -1e30f;
            if (ng     > mg0 + 8) sacc[j][2] = -1e30f;
            if (ng + 1 > mg0 + 8) sacc[j][3] = -1e30f;
            mx0 = fmaxf(mx0, fmaxf(sacc[j][0], sacc[j][1]));
            mx1 = fmaxf(mx1, fmaxf(sacc[j][2], sacc[j][3]));
        }
        mx0 = fmaxf(mx0, __shfl_xor_sync(0xffffffffu, mx0, 1));
        mx0 = fmaxf(mx0, __shfl_xor_sync(0xffffffffu, mx0, 2));
        mx1 = fmaxf(mx1, __shfl_xor_sync(0xffffffffu, mx1, 1));
        mx1 = fmaxf(mx1, __shfl_xor_sync(0xffffffffu, mx1, 2));
        if (tg == 0) {
            pmax[wn * 64 + mr]     = mx0;
            pmax[wn * 64 + mr + 8] = mx1;
        }
        __syncthreads();   // S2

        // softmax in registers; write P as single packed fp16
        float mn0 = fmaxf(m0_, fmaxf(pmax[mr],     pmax[64 + mr]));
        float mn1 = fmaxf(m1_, fmaxf(pmax[mr + 8], pmax[64 + mr + 8]));
        float cr0 = __expf(m0_ - mn0), cr1 = __expf(m1_ - mn1);
        m0_ = mn0; m1_ = mn1;
        float s0 = 0.f, s1 = 0.f;
#pragma unroll
        for (int j = 0; j < 4; j++) {
            float p0 = __expf(sacc[j][0] - mn0), p1 = __expf(sacc[j][1] - mn0);
            float p2 = __expf(sacc[j][2] - mn1), p3 = __expf(sacc[j][3] - mn1);
            s0 += p0 + p1; s1 += p2 + p3;
            int ci = wn * 16 + j * 4 + tg;
            Ph[mr][ci]     = round2h(p0, p1);
            Ph[mr + 8][ci] = round2h(p2, p3);
        }
        s0 += __shfl_xor_sync(0xffffffffu, s0, 1);
        s0 += __shfl_xor_sync(0xffffffffu, s0, 2);
        s1 += __shfl_xor_sync(0xffffffffu, s1, 1);
        s1 += __shfl_xor_sync(0xffffffffu, s1, 2);
        if (tg == 0) {
            psum[wn * 64 + mr]     = s0;
            psum[wn * 64 + mr + 8] = s1;
        }
        __syncthreads();   // S3

        l0_ = l0_ * cr0 + psum[mr]     + psum[64 + mr];
        l1_ = l1_ * cr1 + psum[mr + 8] + psum[64 + mr + 8];
#pragma unroll
        for (int j = 0; j < 4; j++) {
            oacc[j][0] *= cr0; oacc[j][1] *= cr0;
            oacc[j][2] *= cr1; oacc[j][3] *= cr1;
        }

        // O += P @ V (P single fp16, V split: 2 mma; V via ldmatrix.trans)
#pragma unroll
        for (int kb = 0; kb < 32; kb += 8) {
            uint32_t pah[4];
            pah[0] = Ph[mr][kb + tg];
            pah[1] = Ph[mr + 8][kb + tg];
            pah[2] = Ph[mr][kb + tg + 4];
            pah[3] = Ph[mr + 8][kb + tg + 4];
            int krow = kb * 2 + (lane & 15);
#pragma unroll
            for (int j = 0; j < 4; j++) {
                int c0j = wn * 32 + j * 8;
                uint32_t vh0, vh1, vl0, vl1;
                ldm_x2_t(vh0, vh1, vh_base + krow * 144 + c0j * 2);
                ldm_x2_t(vl0, vl1, vl_base + krow * 144 + c0j * 2);
                uint32_t bhf[2] = { vh0, vh1 };
                uint32_t blf[2] = { vl0, vl1 };
                mma_fp16(oacc[j], pah, bhf);
                mma_fp16(oacc[j], pah, blf);
            }
        }
    }

    // epilogue: normalize, store [b,t,c], c = h*64 + d
    {
        float inv0 = 1.f / l0_, inv1 = 1.f / l1_;
        size_t row0 = (size_t)(b * TT + qt * 64 + mr);
#pragma unroll
        for (int j = 0; j < 4; j++) {
            int col = h * DKH + wn * 32 + j * 8 + 2 * tg;
            *reinterpret_cast<float2*>(att + row0 * N_EMBD + col) =
                make_float2(oacc[j][0] * inv0, oacc[j][1] * inv0);
            *reinterpret_cast<float2*>(att + (row0 + 8) * N_EMBD + col) =
                make_float2(oacc[j][2] * inv1, oacc[j][3] * inv1);
        }
    }
}

// ---------------- launch ----------------
extern "C" void kernel_launch(void* const* d_in, const int* in_sizes, int n_in,
                              void* d_out, int out_size)
{
    const float* x  = (const float*)d_in[0];   // [2,2048,1024]
    const float* wa = (const float*)d_in[1];   // [3072,1024]
    const float* wp = (const float*)d_in[2];   // [1024,1024]
    float* out = (float*)d_out;                // [2,2048,1024]

    float* qkv_ptr = nullptr;
    float* att_ptr = nullptr;
    cudaGetSymbolAddress((void**)&qkv_ptr, g_qkv);
    cudaGetSymbolAddress((void**)&att_ptr, g_att);

    cudaFuncSetAttribute(attn_h2,
                         cudaFuncAttributeMaxDynamicSharedMemorySize,
                         ATT_SMEM_BYTES);

    // 1) fused QKV projection
    gemm_nt_h2<<<dim3(C3 / GBN, BT / GBM), 256>>>(x, wa, qkv_ptr, BT, C3, N_EMBD);

    // 2) causal attention
    attn_h2<<<dim3(TT / 64, BB * N_HEAD), 256, ATT_SMEM_BYTES>>>(qkv_ptr, att_ptr);

    // 3) output projection
    gemm_nt_h2<<<dim3(N_EMBD / GBN, BT / GBM), 256>>>(att_ptr, wp, out, BT, N_EMBD, N_EMBD);
}

// round 9
// speedup vs baseline: 1.6183x; 1.3083x over previous
#include <cuda_runtime.h>
#include <cuda_fp16.h>
#include <cstdint>

// ---------------- problem constants ----------------
#define N_EMBD 1024
#define N_HEAD 16
#define DKH    64
#define BB     2
#define TT     2048
#define BT     (BB*TT)     // 4096 rows
#define C3     (3*N_EMBD)  // 3072

// scratch (allocation-free: device globals)
__device__ float  g_qkv[BT * C3];          // [4096][3072] fp32
__device__ __half g_xh[BT * N_EMBD];       // x split hi
__device__ __half g_xl[BT * N_EMBD];       // x split lo
__device__ __half g_wah[C3 * N_EMBD];      // w_attn rounded
__device__ __half g_wph[N_EMBD * N_EMBD];  // w_proj rounded
__device__ __half g_atth[BT * N_EMBD];     // attention out hi
__device__ __half g_attl[BT * N_EMBD];     // attention out lo

// ---------------- fp16 helpers ----------------
__device__ __forceinline__ uint32_t packh2(__half a, __half b) {
    return (uint32_t)__half_as_ushort(a) | ((uint32_t)__half_as_ushort(b) << 16);
}
__device__ __forceinline__ void split2h(float f0, float f1, uint32_t& hi, uint32_t& lo) {
    __half h0 = __float2half_rn(f0);
    __half h1 = __float2half_rn(f1);
    float r0 = f0 - __half2float(h0);
    float r1 = f1 - __half2float(h1);
    hi = packh2(h0, h1);
    lo = packh2(__float2half_rn(r0), __float2half_rn(r1));
}
__device__ __forceinline__ uint32_t round2h(float f0, float f1) {
    return packh2(__float2half_rn(f0), __float2half_rn(f1));
}
__device__ __forceinline__ void mma_fp16(float d[4], const uint32_t a[4], const uint32_t b[2]) {
    asm volatile(
        "mma.sync.aligned.m16n8k16.row.col.f32.f16.f16.f32 "
        "{%0,%1,%2,%3}, {%4,%5,%6,%7}, {%8,%9}, {%0,%1,%2,%3};\n"
        : "+f"(d[0]), "+f"(d[1]), "+f"(d[2]), "+f"(d[3])
        : "r"(a[0]), "r"(a[1]), "r"(a[2]), "r"(a[3]),
          "r"(b[0]), "r"(b[1]));
}
__device__ __forceinline__ void ldsm_x4(uint32_t d[4], uint32_t addr) {
    asm volatile("ldmatrix.sync.aligned.m8n8.x4.shared.b16 {%0,%1,%2,%3}, [%4];"
                 : "=r"(d[0]), "=r"(d[1]), "=r"(d[2]), "=r"(d[3]) : "r"(addr));
}
__device__ __forceinline__ void ldm_x2_t(uint32_t& r0, uint32_t& r1, uint32_t addr) {
    asm volatile("ldmatrix.sync.aligned.m8n8.x2.trans.shared.b16 {%0,%1}, [%2];"
                 : "=r"(r0), "=r"(r1) : "r"(addr));
}
__device__ __forceinline__ void cp16(uint32_t dst, const void* src) {
    asm volatile("cp.async.cg.shared.global [%0], [%1], 16;" :: "r"(dst), "l"(src));
}
#define CP_COMMIT() asm volatile("cp.async.commit_group;" ::: "memory")
#define CP_WAIT(n)  asm volatile("cp.async.wait_group %0;" :: "n"(n) : "memory")

// ---------------- converters ----------------
__global__ __launch_bounds__(256) void conv_split(const float* __restrict__ in,
                                                  __half* __restrict__ oh,
                                                  __half* __restrict__ ol) {
    int i = (blockIdx.x * 256 + threadIdx.x) * 4;
    float4 v = *reinterpret_cast<const float4*>(in + i);
    uint32_t h01, l01, h23, l23;
    split2h(v.x, v.y, h01, l01);
    split2h(v.z, v.w, h23, l23);
    *reinterpret_cast<uint2*>(oh + i) = make_uint2(h01, h23);
    *reinterpret_cast<uint2*>(ol + i) = make_uint2(l01, l23);
}
__global__ __launch_bounds__(256) void conv_round(const float* __restrict__ in,
                                                  __half* __restrict__ oh) {
    int i = (blockIdx.x * 256 + threadIdx.x) * 4;
    float4 v = *reinterpret_cast<const float4*>(in + i);
    *reinterpret_cast<uint2*>(oh + i) = make_uint2(round2h(v.x, v.y), round2h(v.z, v.w));
}

// ---------------- pipelined fp16 NT GEMM ----------------
// C[M,N] = (Ah + Al)[M,K] * Bh[N,K]^T, all fp16 inputs, fp32 out.
// Block 128x128x32, 2-stage cp.async pipeline, warp tile 64x32.
// SMEM (halfs, row stride 40): per buffer Ah@0, Al@5120, Bh@10240; 15360 halfs/buf.
#define PBUF_B 30720
#define GEMM_SMEM (2 * PBUF_B)

__global__ __launch_bounds__(256, 2) void gemm_h_pipe(const __half* __restrict__ Ah,
                                                      const __half* __restrict__ Al,
                                                      const __half* __restrict__ Bh,
                                                      float* __restrict__ Cm,
                                                      int M, int N, int K)
{
    extern __shared__ __half sh[];
    const int tid = threadIdx.x, wid = tid >> 5, lane = tid & 31;
    const int wm = wid >> 2, wn = wid & 3;
    const int r = lane >> 2, tg = lane & 3;
    const int m0 = blockIdx.y * 128, n0 = blockIdx.x * 128;
    const uint32_t sbase = (uint32_t)__cvta_generic_to_shared(sh);

    float acc[4][4][4] = {};

    const int nblk = K / 32;
    auto issue = [&](int i) {
        const int kt = i * 32;
        const uint32_t dbase = sbase + (uint32_t)(i & 1) * PBUF_B;
#pragma unroll
        for (int q = 0; q < 6; q++) {
            int c = q * 256 + tid;          // 0..1535
            int t = c >> 9;                 // 0:Ah 1:Al 2:Bh
            int rr = (c & 511) >> 2;
            int ch = c & 3;
            const __half* src =
                (t == 0 ? Ah + (size_t)(m0 + rr) * K :
                 t == 1 ? Al + (size_t)(m0 + rr) * K :
                          Bh + (size_t)(n0 + rr) * K) + kt + ch * 8;
            cp16(dbase + (uint32_t)(t * 10240 + rr * 80 + ch * 16), src);
        }
    };

    issue(0);
    CP_COMMIT();

    const int arow = (lane & 15);
    const int acol = ((lane >> 4) & 1) * 8;
    const int brow_off = ((lane >> 4) & 1) * 8 + (lane & 7);
    const int bcol = ((lane >> 3) & 1) * 8;

    for (int i = 0; i < nblk; i++) {
        if (i + 1 < nblk) {
            issue(i + 1);
            CP_COMMIT();
            CP_WAIT(1);
        } else {
            CP_WAIT(0);
        }
        __syncthreads();

        const uint32_t abase = sbase + (uint32_t)(i & 1) * PBUF_B;
#pragma unroll
        for (int s = 0; s < 2; s++) {
            const int ks = s * 16;
            uint32_t af_h[4][4], af_l[4][4];
#pragma unroll
            for (int ti = 0; ti < 4; ti++) {
                uint32_t ad = abase +
                    (uint32_t)((wm * 64 + ti * 16 + arow) * 80 + (ks + acol) * 2);
                ldsm_x4(af_h[ti], ad);
                ldsm_x4(af_l[ti], ad + 10240u);
            }
            uint32_t bf[4][2];
#pragma unroll
            for (int g = 0; g < 2; g++) {
                uint32_t bd = abase + 20480u +
                    (uint32_t)((wn * 32 + g * 16 + brow_off) * 80 + (ks + bcol) * 2);
                uint32_t d[4];
                ldsm_x4(d, bd);
                bf[2 * g][0] = d[0]; bf[2 * g][1] = d[1];
                bf[2 * g + 1][0] = d[2]; bf[2 * g + 1][1] = d[3];
            }
#pragma unroll
            for (int ti = 0; ti < 4; ti++)
#pragma unroll
                for (int j = 0; j < 4; j++) {
                    mma_fp16(acc[ti][j], af_h[ti], bf[j]);
                    mma_fp16(acc[ti][j], af_l[ti], bf[j]);
                }
        }
        __syncthreads();
    }

#pragma unroll
    for (int ti = 0; ti < 4; ti++) {
        size_t row0 = (size_t)(m0 + wm * 64 + ti * 16 + r);
#pragma unroll
        for (int j = 0; j < 4; j++) {
            int col = n0 + wn * 32 + j * 8 + 2 * tg;
            *reinterpret_cast<float2*>(Cm + row0 * N + col) =
                make_float2(acc[ti][j][0], acc[ti][j][1]);
            *reinterpret_cast<float2*>(Cm + (row0 + 8) * N + col) =
                make_float2(acc[ti][j][2], acc[ti][j][3]);
        }
    }
}

// ---------------- causal flash attention (fp16 2-term; epilogue -> split fp16) ----------------
#define ATT_SMEM_BYTES 56320

__global__ __launch_bounds__(256) void attn_h2(const float* __restrict__ qkv,
                                               __half* __restrict__ atth,
                                               __half* __restrict__ attl)
{
    extern __shared__ char smc[];
    uint32_t (*Qh)[36] = (uint32_t(*)[36])(smc);
    uint32_t (*Ql)[36] = (uint32_t(*)[36])(smc + 9216);
    uint32_t (*Kh)[36] = (uint32_t(*)[36])(smc + 18432);
    __half (*Vh)[72] = (__half(*)[72])(smc + 27648);
    __half (*Vl)[72] = (__half(*)[72])(smc + 36864);
    uint32_t (*Ph)[36] = (uint32_t(*)[36])(smc + 46080);
    float* pmax = (float*)(smc + 55296);
    float* psum = (float*)(smc + 55808);

    const int tid  = threadIdx.x;
    const int wid  = tid >> 5, lane = tid & 31;
    const int wm   = wid & 3,  wn   = wid >> 2;
    const int r    = lane >> 2, tg  = lane & 3;
    const int qt   = (int)gridDim.x - 1 - (int)blockIdx.x;
    const int bh_  = blockIdx.y;
    const int b    = bh_ >> 4, h = bh_ & 15;

    const uint32_t vh_base = (uint32_t)__cvta_generic_to_shared(Vh);
    const uint32_t vl_base = (uint32_t)__cvta_generic_to_shared(Vl);

#pragma unroll
    for (int it = 0; it < 4; it++) {
        int l = tid + it * 256;
        int row = l >> 4, c4 = l & 15;
        float4 v = *reinterpret_cast<const float4*>(
            qkv + (size_t)(b * TT + qt * 64 + row) * C3 + h * DKH + c4 * 4);
        split2h(v.x * 0.125f, v.y * 0.125f, Qh[row][c4 * 2],     Ql[row][c4 * 2]);
        split2h(v.z * 0.125f, v.w * 0.125f, Qh[row][c4 * 2 + 1], Ql[row][c4 * 2 + 1]);
    }

    const int mr  = wm * 16 + r;
    float m0_ = -1e30f, m1_ = -1e30f;
    float l0_ = 0.f,    l1_ = 0.f;
    float oacc[4][4] = {};

    for (int kt = 0; kt <= qt; kt++) {
        __syncthreads();
#pragma unroll
        for (int it = 0; it < 4; it++) {
            int l = tid + it * 256;
            int row = l >> 4, c4 = l & 15;
            size_t base = (size_t)(b * TT + kt * 64 + row) * C3 + h * DKH + c4 * 4;
            float4 kv = *reinterpret_cast<const float4*>(qkv + base + N_EMBD);
            float4 vv = *reinterpret_cast<const float4*>(qkv + base + 2 * N_EMBD);
            Kh[row][c4 * 2]     = round2h(kv.x, kv.y);
            Kh[row][c4 * 2 + 1] = round2h(kv.z, kv.w);
            uint32_t h01, l01, h23, l23;
            split2h(vv.x, vv.y, h01, l01);
            split2h(vv.z, vv.w, h23, l23);
            uint32_t* vh32 = reinterpret_cast<uint32_t*>(&Vh[row][c4 * 4]);
            uint32_t* vl32 = reinterpret_cast<uint32_t*>(&Vl[row][c4 * 4]);
            vh32[0] = h01; vh32[1] = h23;
            vl32[0] = l01; vl32[1] = l23;
        }
        __syncthreads();

        float sacc[4][4] = {};
#pragma unroll
        for (int kb = 0; kb < 32; kb += 8) {
            uint32_t ah[4], al[4];
            ah[0] = Qh[mr][kb + tg];         al[0] = Ql[mr][kb + tg];
            ah[1] = Qh[mr + 8][kb + tg];     al[1] = Ql[mr + 8][kb + tg];
            ah[2] = Qh[mr][kb + tg + 4];     al[2] = Ql[mr][kb + tg + 4];
            ah[3] = Qh[mr + 8][kb + tg + 4]; al[3] = Ql[mr + 8][kb + tg + 4];
#pragma unroll
            for (int j = 0; j < 4; j++) {
                int nr = wn * 32 + j * 8 + r;
                uint32_t bhf[2] = { Kh[nr][kb + tg], Kh[nr][kb + tg + 4] };
                mma_fp16(sacc[j], ah, bhf);
                mma_fp16(sacc[j], al, bhf);
            }
        }

        const int mg0 = qt * 64 + mr;
        float mx0 = -1e30f, mx1 = -1e30f;
#pragma unroll
        for (int j = 0; j < 4; j++) {
            int ng = kt * 64 + wn * 32 + j * 8 + 2 * tg;
            if (ng     > mg0)     sacc[j][0] = -1e30f;
            if (ng + 1 > mg0)     sacc[j][1] = -1e30f;
            if (ng     > mg0 + 8) sacc[j][2] = -1e30f;
            if (ng + 1 > mg0 + 8) sacc[j][3] = -1e30f;
            mx0 = fmaxf(mx0, fmaxf(sacc[j][0], sacc[j][1]));
            mx1 = fmaxf(mx1, fmaxf(sacc[j][2], sacc[j][3]));
        }
        mx0 = fmaxf(mx0, __shfl_xor_sync(0xffffffffu, mx0, 1));
        mx0 = fmaxf(mx0, __shfl_xor_sync(0xffffffffu, mx0, 2));
        mx1 = fmaxf(mx1, __shfl_xor_sync(0xffffffffu, mx1, 1));
        mx1 = fmaxf(mx1, __shfl_xor_sync(0xffffffffu, mx1, 2));
        if (tg == 0) {
            pmax[wn * 64 + mr]     = mx0;
            pmax[wn * 64 + mr + 8] = mx1;
        }
        __syncthreads();

        float mn0 = fmaxf(m0_, fmaxf(pmax[mr],     pmax[64 + mr]));
        float mn1 = fmaxf(m1_, fmaxf(pmax[mr + 8], pmax[64 + mr + 8]));
        float cr0 = __expf(m0_ - mn0), cr1 = __expf(m1_ - mn1);
        m0_ = mn0; m1_ = mn1;
        float s0 = 0.f, s1 = 0.f;
#pragma unroll
        for (int j = 0; j < 4; j++) {
            float p0 = __expf(sacc[j][0] - mn0), p1 = __expf(sacc[j][1] - mn0);
            float p2 = __expf(sacc[j][2] - mn1), p3 = __expf(sacc[j][3] - mn1);
            s0 += p0 + p1; s1 += p2 + p3;
            int ci = wn * 16 + j * 4 + tg;
            Ph[mr][ci]     = round2h(p0, p1);
            Ph[mr + 8][ci] = round2h(p2, p3);
        }
        s0 += __shfl_xor_sync(0xffffffffu, s0, 1);
        s0 += __shfl_xor_sync(0xffffffffu, s0, 2);
        s1 += __shfl_xor_sync(0xffffffffu, s1, 1);
        s1 += __shfl_xor_sync(0xffffffffu, s1, 2);
        if (tg == 0) {
            psum[wn * 64 + mr]     = s0;
            psum[wn * 64 + mr + 8] = s1;
        }
        __syncthreads();

        l0_ = l0_ * cr0 + psum[mr]     + psum[64 + mr];
        l1_ = l1_ * cr1 + psum[mr + 8] + psum[64 + mr + 8];
#pragma unroll
        for (int j = 0; j < 4; j++) {
            oacc[j][0] *= cr0; oacc[j][1] *= cr0;
            oacc[j][2] *= cr1; oacc[j][3] *= cr1;
        }

#pragma unroll
        for (int kb = 0; kb < 32; kb += 8) {
            uint32_t pah[4];
            pah[0] = Ph[mr][kb + tg];
            pah[1] = Ph[mr + 8][kb + tg];
            pah[2] = Ph[mr][kb + tg + 4];
            pah[3] = Ph[mr + 8][kb + tg + 4];
            int krow = kb * 2 + (lane & 15);
#pragma unroll
            for (int j = 0; j < 4; j++) {
                int c0j = wn * 32 + j * 8;
                uint32_t vh0, vh1, vl0, vl1;
                ldm_x2_t(vh0, vh1, vh_base + krow * 144 + c0j * 2);
                ldm_x2_t(vl0, vl1, vl_base + krow * 144 + c0j * 2);
                uint32_t bhf[2] = { vh0, vh1 };
                uint32_t blf[2] = { vl0, vl1 };
                mma_fp16(oacc[j], pah, bhf);
                mma_fp16(oacc[j], pah, blf);
            }
        }
    }

    // epilogue: normalize, split to fp16 hi/lo, store
    {
        float inv0 = 1.f / l0_, inv1 = 1.f / l1_;
        size_t row0 = (size_t)(b * TT + qt * 64 + mr);
#pragma unroll
        for (int j = 0; j < 4; j++) {
            int col = h * DKH + wn * 32 + j * 8 + 2 * tg;
            uint32_t hu, lu;
            split2h(oacc[j][0] * inv0, oacc[j][1] * inv0, hu, lu);
            *reinterpret_cast<uint32_t*>(atth + row0 * N_EMBD + col) = hu;
            *reinterpret_cast<uint32_t*>(attl + row0 * N_EMBD + col) = lu;
            split2h(oacc[j][2] * inv1, oacc[j][3] * inv1, hu, lu);
            *reinterpret_cast<uint32_t*>(atth + (row0 + 8) * N_EMBD + col) = hu;
            *reinterpret_cast<uint32_t*>(attl + (row0 + 8) * N_EMBD + col) = lu;
        }
    }
}

// ---------------- launch ----------------
extern "C" void kernel_launch(void* const* d_in, const int* in_sizes, int n_in,
                              void* d_out, int out_size)
{
    const float* x  = (const float*)d_in[0];   // [2,2048,1024]
    const float* wa = (const float*)d_in[1];   // [3072,1024]
    const float* wp = (const float*)d_in[2];   // [1024,1024]
    float* out = (float*)d_out;                // [2,2048,1024]

    float *qkv_ptr = nullptr;
    __half *xh, *xl, *wah, *wph, *atth, *attl;
    cudaGetSymbolAddress((void**)&qkv_ptr, g_qkv);
    cudaGetSymbolAddress((void**)&xh, g_xh);
    cudaGetSymbolAddress((void**)&xl, g_xl);
    cudaGetSymbolAddress((void**)&wah, g_wah);
    cudaGetSymbolAddress((void**)&wph, g_wph);
    cudaGetSymbolAddress((void**)&atth, g_atth);
    cudaGetSymbolAddress((void**)&attl, g_attl);

    cudaFuncSetAttribute(gemm_h_pipe,
                         cudaFuncAttributeMaxDynamicSharedMemorySize, GEMM_SMEM);
    cudaFuncSetAttribute(attn_h2,
                         cudaFuncAttributeMaxDynamicSharedMemorySize, ATT_SMEM_BYTES);

    // 0) precision prep
    conv_split<<<BT * N_EMBD / 1024, 256>>>(x, xh, xl);
    conv_round<<<C3 * N_EMBD / 1024, 256>>>(wa, wah);
    conv_round<<<N_EMBD * N_EMBD / 1024, 256>>>(wp, wph);

    // 1) fused QKV projection: [4096,3072]
    gemm_h_pipe<<<dim3(C3 / 128, BT / 128), 256, GEMM_SMEM>>>(
        xh, xl, wah, qkv_ptr, BT, C3, N_EMBD);

    // 2) causal attention (emits split fp16 output)
    attn_h2<<<dim3(TT / 64, BB * N_HEAD), 256, ATT_SMEM_BYTES>>>(qkv_ptr, atth, attl);

    // 3) output projection: [4096,1024]
    gemm_h_pipe<<<dim3(N_EMBD / 128, BT / 128), 256, GEMM_SMEM>>>(
        atth, attl, wph, out, BT, N_EMBD, N_EMBD);
}

// round 12
// speedup vs baseline: 1.6841x; 1.0406x over previous
#include <cuda_runtime.h>
#include <cuda_fp16.h>
#include <cstdint>

// ---------------- problem constants ----------------
#define N_EMBD 1024
#define N_HEAD 16
#define DKH    64
#define BB     2
#define TT     2048
#define BT     (BB*TT)     // 4096 rows
#define C3     (3*N_EMBD)  // 3072

// scratch (allocation-free: device globals)
__device__ __half g_xh[BT * N_EMBD];       // x split hi
__device__ __half g_xl[BT * N_EMBD];       // x split lo
__device__ __half g_wah[C3 * N_EMBD];      // w_attn rounded
__device__ __half g_wph[N_EMBD * N_EMBD];  // w_proj rounded
__device__ __half g_qkvh[BT * C3];         // qkv split hi (Q pre-scaled 0.125)
__device__ __half g_qkvl[BT * C3];         // qkv split lo
__device__ __half g_atth[BT * N_EMBD];     // attention out hi
__device__ __half g_attl[BT * N_EMBD];     // attention out lo

// ---------------- fp16 helpers ----------------
__device__ __forceinline__ uint32_t packh2(__half a, __half b) {
    return (uint32_t)__half_as_ushort(a) | ((uint32_t)__half_as_ushort(b) << 16);
}
__device__ __forceinline__ void split2h(float f0, float f1, uint32_t& hi, uint32_t& lo) {
    __half h0 = __float2half_rn(f0);
    __half h1 = __float2half_rn(f1);
    float r0 = f0 - __half2float(h0);
    float r1 = f1 - __half2float(h1);
    hi = packh2(h0, h1);
    lo = packh2(__float2half_rn(r0), __float2half_rn(r1));
}
__device__ __forceinline__ uint32_t round2h(float f0, float f1) {
    return packh2(__float2half_rn(f0), __float2half_rn(f1));
}
__device__ __forceinline__ void mma_fp16(float d[4], const uint32_t a[4], const uint32_t b[2]) {
    asm volatile(
        "mma.sync.aligned.m16n8k16.row.col.f32.f16.f16.f32 "
        "{%0,%1,%2,%3}, {%4,%5,%6,%7}, {%8,%9}, {%0,%1,%2,%3};\n"
        : "+f"(d[0]), "+f"(d[1]), "+f"(d[2]), "+f"(d[3])
        : "r"(a[0]), "r"(a[1]), "r"(a[2]), "r"(a[3]),
          "r"(b[0]), "r"(b[1]));
}
__device__ __forceinline__ void ldsm_x4(uint32_t d[4], uint32_t addr) {
    asm volatile("ldmatrix.sync.aligned.m8n8.x4.shared.b16 {%0,%1,%2,%3}, [%4];"
                 : "=r"(d[0]), "=r"(d[1]), "=r"(d[2]), "=r"(d[3]) : "r"(addr));
}
__device__ __forceinline__ void ldm_x2_t(uint32_t& r0, uint32_t& r1, uint32_t addr) {
    asm volatile("ldmatrix.sync.aligned.m8n8.x2.trans.shared.b16 {%0,%1}, [%2];"
                 : "=r"(r0), "=r"(r1) : "r"(addr));
}
__device__ __forceinline__ void cp16(uint32_t dst, const void* src) {
    asm volatile("cp.async.cg.shared.global [%0], [%1], 16;" :: "r"(dst), "l"(src));
}
#define CP_COMMIT() asm volatile("cp.async.commit_group;" ::: "memory")
#define CP_WAIT(n)  asm volatile("cp.async.wait_group %0;" :: "n"(n) : "memory")

// ---------------- converters ----------------
__global__ __launch_bounds__(256) void conv_split(const float* __restrict__ in,
                                                  __half* __restrict__ oh,
                                                  __half* __restrict__ ol) {
    int i = (blockIdx.x * 256 + threadIdx.x) * 4;
    float4 v = *reinterpret_cast<const float4*>(in + i);
    uint32_t h01, l01, h23, l23;
    split2h(v.x, v.y, h01, l01);
    split2h(v.z, v.w, h23, l23);
    *reinterpret_cast<uint2*>(oh + i) = make_uint2(h01, h23);
    *reinterpret_cast<uint2*>(ol + i) = make_uint2(l01, l23);
}
__global__ __launch_bounds__(256) void conv_round(const float* __restrict__ in,
                                                  __half* __restrict__ oh) {
    int i = (blockIdx.x * 256 + threadIdx.x) * 4;
    float4 v = *reinterpret_cast<const float4*>(in + i);
    *reinterpret_cast<uint2*>(oh + i) = make_uint2(round2h(v.x, v.y), round2h(v.z, v.w));
}

// ---------------- pipelined fp16 NT GEMM ----------------
// C = (Ah+Al)[M,K] * Bh[N,K]^T. Block 128x128x32, 2-stage cp.async, warp tile 64x32.
// SPLIT_OUT: write C as split fp16 (hi/lo), pre-scaling cols < N_EMBD by 0.125 (Q).
#define PBUF_B 30720
#define GEMM_SMEM (2 * PBUF_B)

template<bool SPLIT_OUT>
__global__ __launch_bounds__(256, 2) void gemm_h_pipe(const __half* __restrict__ Ah,
                                                      const __half* __restrict__ Al,
                                                      const __half* __restrict__ Bh,
                                                      float* __restrict__ Cf,
                                                      __half* __restrict__ Ch,
                                                      __half* __restrict__ Cl,
                                                      int M, int N, int K)
{
    extern __shared__ __half sh[];
    const int tid = threadIdx.x, wid = tid >> 5, lane = tid & 31;
    const int wm = wid >> 2, wn = wid & 3;
    const int r = lane >> 2, tg = lane & 3;
    const int m0 = blockIdx.y * 128, n0 = blockIdx.x * 128;
    const uint32_t sbase = (uint32_t)__cvta_generic_to_shared(sh);

    float acc[4][4][4] = {};

    const int nblk = K / 32;
    auto issue = [&](int i) {
        const int kt = i * 32;
        const uint32_t dbase = sbase + (uint32_t)(i & 1) * PBUF_B;
#pragma unroll
        for (int q = 0; q < 6; q++) {
            int c = q * 256 + tid;
            int t = c >> 9;
            int rr = (c & 511) >> 2;
            int ch = c & 3;
            const __half* src =
                (t == 0 ? Ah + (size_t)(m0 + rr) * K :
                 t == 1 ? Al + (size_t)(m0 + rr) * K :
                          Bh + (size_t)(n0 + rr) * K) + kt + ch * 8;
            cp16(dbase + (uint32_t)(t * 10240 + rr * 80 + ch * 16), src);
        }
    };

    issue(0);
    CP_COMMIT();

    const int arow = (lane & 15);
    const int acol = ((lane >> 4) & 1) * 8;
    const int brow_off = ((lane >> 4) & 1) * 8 + (lane & 7);
    const int bcol = ((lane >> 3) & 1) * 8;

    for (int i = 0; i < nblk; i++) {
        if (i + 1 < nblk) {
            issue(i + 1);
            CP_COMMIT();
            CP_WAIT(1);
        } else {
            CP_WAIT(0);
        }
        __syncthreads();

        const uint32_t abase = sbase + (uint32_t)(i & 1) * PBUF_B;
#pragma unroll
        for (int s = 0; s < 2; s++) {
            const int ks = s * 16;
            uint32_t af_h[4][4], af_l[4][4];
#pragma unroll
            for (int ti = 0; ti < 4; ti++) {
                uint32_t ad = abase +
                    (uint32_t)((wm * 64 + ti * 16 + arow) * 80 + (ks + acol) * 2);
                ldsm_x4(af_h[ti], ad);
                ldsm_x4(af_l[ti], ad + 10240u);
            }
            uint32_t bf[4][2];
#pragma unroll
            for (int g = 0; g < 2; g++) {
                uint32_t bd = abase + 20480u +
                    (uint32_t)((wn * 32 + g * 16 + brow_off) * 80 + (ks + bcol) * 2);
                uint32_t d[4];
                ldsm_x4(d, bd);
                bf[2 * g][0] = d[0]; bf[2 * g][1] = d[1];
                bf[2 * g + 1][0] = d[2]; bf[2 * g + 1][1] = d[3];
            }
#pragma unroll
            for (int ti = 0; ti < 4; ti++)
#pragma unroll
                for (int j = 0; j < 4; j++) {
                    mma_fp16(acc[ti][j], af_h[ti], bf[j]);
                    mma_fp16(acc[ti][j], af_l[ti], bf[j]);
                }
        }
        __syncthreads();
    }

#pragma unroll
    for (int ti = 0; ti < 4; ti++) {
        size_t row0 = (size_t)(m0 + wm * 64 + ti * 16 + r);
#pragma unroll
        for (int j = 0; j < 4; j++) {
            int col = n0 + wn * 32 + j * 8 + 2 * tg;
            if (SPLIT_OUT) {
                float sc = (col < N_EMBD) ? 0.125f : 1.0f;   // pre-scale Q block
                uint32_t hu, lu;
                split2h(acc[ti][j][0] * sc, acc[ti][j][1] * sc, hu, lu);
                *reinterpret_cast<uint32_t*>(Ch + row0 * N + col) = hu;
                *reinterpret_cast<uint32_t*>(Cl + row0 * N + col) = lu;
                split2h(acc[ti][j][2] * sc, acc[ti][j][3] * sc, hu, lu);
                *reinterpret_cast<uint32_t*>(Ch + (row0 + 8) * N + col) = hu;
                *reinterpret_cast<uint32_t*>(Cl + (row0 + 8) * N + col) = lu;
            } else {
                *reinterpret_cast<float2*>(Cf + row0 * N + col) =
                    make_float2(acc[ti][j][0], acc[ti][j][1]);
                *reinterpret_cast<float2*>(Cf + (row0 + 8) * N + col) =
                    make_float2(acc[ti][j][2], acc[ti][j][3]);
            }
        }
    }
}

// ---------------- causal flash attention (cp.async double-buffered K/V) ----------------
// smem bytes (row stride 144): Qh 0, Ql 9216, buf{0,1}: Kh/Vh/Vl 3x9216 each,
// Ph 73728, pmax 82944, psum 83456 -> 83968 total
#define AQH 0
#define AQL 9216
#define ABUF0 18432
#define ABUFSZ 27648
#define APH 73728
#define APMAX 82944
#define APSUM 83456
#define ATT_SMEM_BYTES 83968

__global__ __launch_bounds__(256) void attn_h3(const __half* __restrict__ qkvh,
                                               const __half* __restrict__ qkvl,
                                               __half* __restrict__ atth,
                                               __half* __restrict__ attl)
{
    extern __shared__ char smc[];
    uint32_t (*Ph)[36] = (uint32_t(*)[36])(smc + APH);
    float* pmax = (float*)(smc + APMAX);
    float* psum = (float*)(smc + APSUM);

    const int tid  = threadIdx.x;
    const int wid  = tid >> 5, lane = tid & 31;
    const int wm   = wid & 3,  wn   = wid >> 2;
    const int r    = lane >> 2, tg  = lane & 3;
    const int qt   = (int)gridDim.x - 1 - (int)blockIdx.x;   // big tiles first
    const int bh_  = blockIdx.y;
    const int b    = bh_ >> 4, h = bh_ & 15;
    const uint32_t sbase = (uint32_t)__cvta_generic_to_shared(smc);

    const int srow = tid >> 2;          // 0..63
    const int sch  = (tid & 3) * 2;     // chunk pairs 0,2,4,6

    auto issue_kv = [&](int kt) {
        const uint32_t dbase = sbase + ABUF0 + (uint32_t)(kt & 1) * ABUFSZ;
        size_t rg = (size_t)(b * TT + kt * 64 + srow) * C3 + h * DKH;
        const __half* ks  = qkvh + rg + N_EMBD;
        const __half* vhs = qkvh + rg + 2 * N_EMBD;
        const __half* vls = qkvl + rg + 2 * N_EMBD;
        uint32_t d = dbase + (uint32_t)(srow * 144 + sch * 16);
        cp16(d,                ks  + sch * 8);
        cp16(d + 16,           ks  + sch * 8 + 8);
        cp16(d + 9216,         vhs + sch * 8);
        cp16(d + 9216 + 16,    vhs + sch * 8 + 8);
        cp16(d + 18432,        vls + sch * 8);
        cp16(d + 18432 + 16,   vls + sch * 8 + 8);
    };

    // prologue: stage Q + first K/V tile
    {
        size_t rg = (size_t)(b * TT + qt * 64 + srow) * C3 + h * DKH;
        uint32_t d = sbase + (uint32_t)(srow * 144 + sch * 16);
        cp16(d,               qkvh + rg + sch * 8);
        cp16(d + 16,          qkvh + rg + sch * 8 + 8);
        cp16(d + AQL,         qkvl + rg + sch * 8);
        cp16(d + AQL + 16,    qkvl + rg + sch * 8 + 8);
    }
    issue_kv(0);
    CP_COMMIT();
    CP_WAIT(0);
    __syncthreads();

    // hoist Q fragments into registers (whole kernel)
    const int arow = (lane & 15);
    const int acol = ((lane >> 4) & 1) * 8;
    uint32_t qhf[4][4], qlf[4][4];
#pragma unroll
    for (int s = 0; s < 4; s++) {
        uint32_t ad = sbase + AQH +
            (uint32_t)((wm * 16 + arow) * 144 + (s * 16 + acol) * 2);
        ldsm_x4(qhf[s], ad);
        ldsm_x4(qlf[s], ad + AQL);
    }

    const int mr = wm * 16 + r;
    const int brow_off = ((lane >> 4) & 1) * 8 + (lane & 7);
    const int bcol = ((lane >> 3) & 1) * 8;
    float m0_ = -1e30f, m1_ = -1e30f, l0_ = 0.f, l1_ = 0.f;
    float oacc[4][4] = {};

    for (int kt = 0; kt <= qt; kt++) {
        if (kt < qt) {
            issue_kv(kt + 1);
            CP_COMMIT();
            CP_WAIT(1);
        } else {
            CP_WAIT(0);
        }
        __syncthreads();   // B1: tile kt ready

        const uint32_t kb_base = sbase + ABUF0 + (uint32_t)(kt & 1) * ABUFSZ;
        const uint32_t vh_base = kb_base + 9216u;
        const uint32_t vl_base = kb_base + 18432u;

        // S = Q K^T  (Q split 2-term, K single fp16; K via ldsm)
        float sacc[4][4] = {};
#pragma unroll
        for (int s = 0; s < 4; s++) {
            uint32_t bf[4][2];
#pragma unroll
            for (int g = 0; g < 2; g++) {
                uint32_t bd = kb_base +
                    (uint32_t)((wn * 32 + g * 16 + brow_off) * 144 + (s * 16 + bcol) * 2);
                uint32_t d[4];
                ldsm_x4(d, bd);
                bf[2 * g][0] = d[0]; bf[2 * g][1] = d[1];
                bf[2 * g + 1][0] = d[2]; bf[2 * g + 1][1] = d[3];
            }
#pragma unroll
            for (int j = 0; j < 4; j++) {
                mma_fp16(sacc[j], qhf[s], bf[j]);
                mma_fp16(sacc[j], qlf[s], bf[j]);
            }
        }

        // mask + per-row max (warp partial)
        const int mg0 = qt * 64 + mr;
        float mx0 = -1e30f, mx1 = -1e30f;
#pragma unroll
        for (int j = 0; j < 4; j++) {
            int ng = kt * 64 + wn * 32 + j * 8 + 2 * tg;
            if (ng     > mg0)     sacc[j][0] = -1e30f;
            if (ng + 1 > mg0)     sacc[j][1] = -1e30f;
            if (ng     > mg0 + 8) sacc[j][2] = -1e30f;
            if (ng + 1 > mg0 + 8) sacc[j][3] = -1e30f;
            mx0 = fmaxf(mx0, fmaxf(sacc[j][0], sacc[j][1]));
            mx1 = fmaxf(mx1, fmaxf(sacc[j][2], sacc[j][3]));
        }
        mx0 = fmaxf(mx0, __shfl_xor_sync(0xffffffffu, mx0, 1));
        mx0 = fmaxf(mx0, __shfl_xor_sync(0xffffffffu, mx0, 2));
        mx1 = fmaxf(mx1, __shfl_xor_sync(0xffffffffu, mx1, 1));
        mx1 = fmaxf(mx1, __shfl_xor_sync(0xffffffffu, mx1, 2));
        if (tg == 0) {
            pmax[wn * 64 + mr]     = mx0;
            pmax[wn * 64 + mr + 8] = mx1;
        }
        __syncthreads();   // B2

        float mn0 = fmaxf(m0_, fmaxf(pmax[mr],     pmax[64 + mr]));
        float mn1 = fmaxf(m1_, fmaxf(pmax[mr + 8], pmax[64 + mr + 8]));
        float cr0 = __expf(m0_ - mn0), cr1 = __expf(m1_ - mn1);
        m0_ = mn0; m1_ = mn1;
        float s0 = 0.f, s1 = 0.f;
#pragma unroll
        for (int j = 0; j < 4; j++) {
            float p0 = __expf(sacc[j][0] - mn0), p1 = __expf(sacc[j][1] - mn0);
            float p2 = __expf(sacc[j][2] - mn1), p3 = __expf(sacc[j][3] - mn1);
            s0 += p0 + p1; s1 += p2 + p3;
            int ci = wn * 16 + j * 4 + tg;
            Ph[mr][ci]     = round2h(p0, p1);
            Ph[mr + 8][ci] = round2h(p2, p3);
        }
        s0 += __shfl_xor_sync(0xffffffffu, s0, 1);
        s0 += __shfl_xor_sync(0xffffffffu, s0, 2);
        s1 += __shfl_xor_sync(0xffffffffu, s1, 1);
        s1 += __shfl_xor_sync(0xffffffffu, s1, 2);
        if (tg == 0) {
            psum[wn * 64 + mr]     = s0;
            psum[wn * 64 + mr + 8] = s1;
        }
        __syncthreads();   // B3

        l0_ = l0_ * cr0 + psum[mr]     + psum[64 + mr];
        l1_ = l1_ * cr1 + psum[mr + 8] + psum[64 + mr + 8];
#pragma unroll
        for (int j = 0; j < 4; j++) {
            oacc[j][0] *= cr0; oacc[j][1] *= cr0;
            oacc[j][2] *= cr1; oacc[j][3] *= cr1;
        }

        // O += P @ V (P single fp16, V split; V via ldmatrix.trans)
#pragma unroll
        for (int kb = 0; kb < 32; kb += 8) {
            uint32_t pah[4];
            pah[0] = Ph[mr][kb + tg];
            pah[1] = Ph[mr + 8][kb + tg];
            pah[2] = Ph[mr][kb + tg + 4];
            pah[3] = Ph[mr + 8][kb + tg + 4];
            int krow = kb * 2 + (lane & 15);
#pragma unroll
            for (int j = 0; j < 4; j++) {
                int c0j = wn * 32 + j * 8;
                uint32_t vh0, vh1, vl0, vl1;
                ldm_x2_t(vh0, vh1, vh_base + (uint32_t)(krow * 144 + c0j * 2));
                ldm_x2_t(vl0, vl1, vl_base + (uint32_t)(krow * 144 + c0j * 2));
                uint32_t bhf[2] = { vh0, vh1 };
                uint32_t blf[2] = { vl0, vl1 };
                mma_fp16(oacc[j], pah, bhf);
                mma_fp16(oacc[j], pah, blf);
            }
        }
        __syncthreads();   // B4: buffer reads done before next issue overwrites
    }

    // epilogue: normalize, split to fp16 hi/lo, store
    {
        float inv0 = 1.f / l0_, inv1 = 1.f / l1_;
        size_t row0 = (size_t)(b * TT + qt * 64 + mr);
#pragma unroll
        for (int j = 0; j < 4; j++) {
            int col = h * DKH + wn * 32 + j * 8 + 2 * tg;
            uint32_t hu, lu;
            split2h(oacc[j][0] * inv0, oacc[j][1] * inv0, hu, lu);
            *reinterpret_cast<uint32_t*>(atth + row0 * N_EMBD + col) = hu;
            *reinterpret_cast<uint32_t*>(attl + row0 * N_EMBD + col) = lu;
            split2h(oacc[j][2] * inv1, oacc[j][3] * inv1, hu, lu);
            *reinterpret_cast<uint32_t*>(atth + (row0 + 8) * N_EMBD + col) = hu;
            *reinterpret_cast<uint32_t*>(attl + (row0 + 8) * N_EMBD + col) = lu;
        }
    }
}

// ---------------- launch ----------------
extern "C" void kernel_launch(void* const* d_in, const int* in_sizes, int n_in,
                              void* d_out, int out_size)
{
    const float* x  = (const float*)d_in[0];   // [2,2048,1024]
    const float* wa = (const float*)d_in[1];   // [3072,1024]
    const float* wp = (const float*)d_in[2];   // [1024,1024]
    float* out = (float*)d_out;                // [2,2048,1024]

    __half *xh, *xl, *wah, *wph, *qkvh, *qkvl, *atth, *attl;
    cudaGetSymbolAddress((void**)&xh, g_xh);
    cudaGetSymbolAddress((void**)&xl, g_xl);
    cudaGetSymbolAddress((void**)&wah, g_wah);
    cudaGetSymbolAddress((void**)&wph, g_wph);
    cudaGetSymbolAddress((void**)&qkvh, g_qkvh);
    cudaGetSymbolAddress((void**)&qkvl, g_qkvl);
    cudaGetSymbolAddress((void**)&atth, g_atth);
    cudaGetSymbolAddress((void**)&attl, g_attl);

    cudaFuncSetAttribute(gemm_h_pipe<true>,
                         cudaFuncAttributeMaxDynamicSharedMemorySize, GEMM_SMEM);
    cudaFuncSetAttribute(gemm_h_pipe<false>,
                         cudaFuncAttributeMaxDynamicSharedMemorySize, GEMM_SMEM);
    cudaFuncSetAttribute(attn_h3,
                         cudaFuncAttributeMaxDynamicSharedMemorySize, ATT_SMEM_BYTES);

    // 0) precision prep
    conv_split<<<BT * N_EMBD / 1024, 256>>>(x, xh, xl);
    conv_round<<<C3 * N_EMBD / 1024, 256>>>(wa, wah);
    conv_round<<<N_EMBD * N_EMBD / 1024, 256>>>(wp, wph);

    // 1) fused QKV projection -> split fp16 (Q pre-scaled by 0.125)
    gemm_h_pipe<true><<<dim3(C3 / 128, BT / 128), 256, GEMM_SMEM>>>(
        xh, xl, wah, nullptr, qkvh, qkvl, BT, C3, N_EMBD);

    // 2) causal attention (pure fp16 cp.async staging)
    attn_h3<<<dim3(TT / 64, BB * N_HEAD), 256, ATT_SMEM_BYTES>>>(qkvh, qkvl, atth, attl);

    // 3) output projection -> fp32 out
    gemm_h_pipe<false><<<dim3(N_EMBD / 128, BT / 128), 256, GEMM_SMEM>>>(
        atth, attl, wph, out, nullptr, nullptr, BT, N_EMBD, N_EMBD);
}

// round 14
// speedup vs baseline: 1.7840x; 1.0593x over previous
#include <cuda_runtime.h>
#include <cuda_fp16.h>
#include <cstdint>

// ---------------- problem constants ----------------
#define N_EMBD 1024
#define N_HEAD 16
#define DKH    64
#define BB     2
#define TT     2048
#define BT     (BB*TT)     // 4096 rows
#define C3     (3*N_EMBD)  // 3072

// scratch (allocation-free: device globals)
__device__ __half g_xh[BT * N_EMBD];       // x split hi
__device__ __half g_xl[BT * N_EMBD];       // x split lo
__device__ __half g_wah[C3 * N_EMBD];      // w_attn rounded
__device__ __half g_wph[N_EMBD * N_EMBD];  // w_proj rounded
__device__ __half g_qkvh[BT * C3];         // qkv split hi (Q pre-scaled 0.125)
__device__ __half g_qkvl[BT * C3];         // qkv split lo
__device__ __half g_atth[BT * N_EMBD];     // attention out hi
__device__ __half g_attl[BT * N_EMBD];     // attention out lo

// ---------------- fp16 helpers ----------------
__device__ __forceinline__ uint32_t packh2(__half a, __half b) {
    return (uint32_t)__half_as_ushort(a) | ((uint32_t)__half_as_ushort(b) << 16);
}
__device__ __forceinline__ void split2h(float f0, float f1, uint32_t& hi, uint32_t& lo) {
    __half h0 = __float2half_rn(f0);
    __half h1 = __float2half_rn(f1);
    float r0 = f0 - __half2float(h0);
    float r1 = f1 - __half2float(h1);
    hi = packh2(h0, h1);
    lo = packh2(__float2half_rn(r0), __float2half_rn(r1));
}
__device__ __forceinline__ uint32_t round2h(float f0, float f1) {
    return packh2(__float2half_rn(f0), __float2half_rn(f1));
}
__device__ __forceinline__ void mma_fp16(float d[4], const uint32_t a[4], const uint32_t b[2]) {
    asm volatile(
        "mma.sync.aligned.m16n8k16.row.col.f32.f16.f16.f32 "
        "{%0,%1,%2,%3}, {%4,%5,%6,%7}, {%8,%9}, {%0,%1,%2,%3};\n"
        : "+f"(d[0]), "+f"(d[1]), "+f"(d[2]), "+f"(d[3])
        : "r"(a[0]), "r"(a[1]), "r"(a[2]), "r"(a[3]),
          "r"(b[0]), "r"(b[1]));
}
__device__ __forceinline__ void ldsm_x4(uint32_t d[4], uint32_t addr) {
    asm volatile("ldmatrix.sync.aligned.m8n8.x4.shared.b16 {%0,%1,%2,%3}, [%4];"
                 : "=r"(d[0]), "=r"(d[1]), "=r"(d[2]), "=r"(d[3]) : "r"(addr));
}
__device__ __forceinline__ void ldm_x2_t(uint32_t& r0, uint32_t& r1, uint32_t addr) {
    asm volatile("ldmatrix.sync.aligned.m8n8.x2.trans.shared.b16 {%0,%1}, [%2];"
                 : "=r"(r0), "=r"(r1) : "r"(addr));
}
__device__ __forceinline__ void cp16(uint32_t dst, const void* src) {
    asm volatile("cp.async.cg.shared.global [%0], [%1], 16;" :: "r"(dst), "l"(src));
}
#define CP_COMMIT() asm volatile("cp.async.commit_group;" ::: "memory")
#define CP_WAIT(n)  asm volatile("cp.async.wait_group %0;" :: "n"(n) : "memory")

// ---------------- converters ----------------
__global__ __launch_bounds__(256) void conv_split(const float* __restrict__ in,
                                                  __half* __restrict__ oh,
                                                  __half* __restrict__ ol) {
    int i = (blockIdx.x * 256 + threadIdx.x) * 4;
    float4 v = *reinterpret_cast<const float4*>(in + i);
    uint32_t h01, l01, h23, l23;
    split2h(v.x, v.y, h01, l01);
    split2h(v.z, v.w, h23, l23);
    *reinterpret_cast<uint2*>(oh + i) = make_uint2(h01, h23);
    *reinterpret_cast<uint2*>(ol + i) = make_uint2(l01, l23);
}
__global__ __launch_bounds__(256) void conv_round(const float* __restrict__ in,
                                                  __half* __restrict__ oh) {
    int i = (blockIdx.x * 256 + threadIdx.x) * 4;
    float4 v = *reinterpret_cast<const float4*>(in + i);
    *reinterpret_cast<uint2*>(oh + i) = make_uint2(round2h(v.x, v.y), round2h(v.z, v.w));
}

// ---------------- pipelined fp16 NT GEMM (K-block 64) ----------------
// C = (Ah+Al)[M,K] * Bh[N,K]^T. Block 128x128x64, 2-stage cp.async, warp tile 64x32.
// SMEM per buffer (row stride 144B = 72 halfs): Ah@0, Al@18432, Bh@36864 -> 55296 B.
#define PBUF_B 55296
#define GEMM_SMEM (2 * PBUF_B)

template<bool SPLIT_OUT>
__global__ __launch_bounds__(256, 2) void gemm_h_pipe(const __half* __restrict__ Ah,
                                                      const __half* __restrict__ Al,
                                                      const __half* __restrict__ Bh,
                                                      float* __restrict__ Cf,
                                                      __half* __restrict__ Ch,
                                                      __half* __restrict__ Cl,
                                                      int M, int N, int K)
{
    extern __shared__ __half sh[];
    const int tid = threadIdx.x, wid = tid >> 5, lane = tid & 31;
    const int wm = wid >> 2, wn = wid & 3;
    const int r = lane >> 2, tg = lane & 3;
    const int m0 = blockIdx.y * 128, n0 = blockIdx.x * 128;
    const uint32_t sbase = (uint32_t)__cvta_generic_to_shared(sh);

    float acc[4][4][4] = {};

    const int nblk = K / 64;
    auto issue = [&](int i) {
        const int kt = i * 64;
        const uint32_t dbase = sbase + (uint32_t)(i & 1) * PBUF_B;
#pragma unroll
        for (int q = 0; q < 12; q++) {
            int c = q * 256 + tid;          // 0..3071
            int t = c >> 10;                // 0:Ah 1:Al 2:Bh
            int rem = c & 1023;
            int rr = rem >> 3;              // row 0..127
            int ch = rem & 7;               // 16B chunk 0..7
            const __half* src =
                (t == 0 ? Ah + (size_t)(m0 + rr) * K :
                 t == 1 ? Al + (size_t)(m0 + rr) * K :
                          Bh + (size_t)(n0 + rr) * K) + kt + ch * 8;
            cp16(dbase + (uint32_t)(t * 18432 + rr * 144 + ch * 16), src);
        }
    };

    issue(0);
    CP_COMMIT();

    const int arow = (lane & 15);
    const int acol = ((lane >> 4) & 1) * 8;
    const int brow_off = ((lane >> 4) & 1) * 8 + (lane & 7);
    const int bcol = ((lane >> 3) & 1) * 8;

    for (int i = 0; i < nblk; i++) {
        if (i + 1 < nblk) {
            issue(i + 1);
            CP_COMMIT();
            CP_WAIT(1);
        } else {
            CP_WAIT(0);
        }
        __syncthreads();

        const uint32_t abase = sbase + (uint32_t)(i & 1) * PBUF_B;
#pragma unroll
        for (int s = 0; s < 4; s++) {
            const int ks = s * 16;
            uint32_t af_h[4][4], af_l[4][4];
#pragma unroll
            for (int ti = 0; ti < 4; ti++) {
                uint32_t ad = abase +
                    (uint32_t)((wm * 64 + ti * 16 + arow) * 144 + (ks + acol) * 2);
                ldsm_x4(af_h[ti], ad);
                ldsm_x4(af_l[ti], ad + 18432u);
            }
            uint32_t bf[4][2];
#pragma unroll
            for (int g = 0; g < 2; g++) {
                uint32_t bd = abase + 36864u +
                    (uint32_t)((wn * 32 + g * 16 + brow_off) * 144 + (ks + bcol) * 2);
                uint32_t d[4];
                ldsm_x4(d, bd);
                bf[2 * g][0] = d[0]; bf[2 * g][1] = d[1];
                bf[2 * g + 1][0] = d[2]; bf[2 * g + 1][1] = d[3];
            }
#pragma unroll
            for (int ti = 0; ti < 4; ti++)
#pragma unroll
                for (int j = 0; j < 4; j++) {
                    mma_fp16(acc[ti][j], af_h[ti], bf[j]);
                    mma_fp16(acc[ti][j], af_l[ti], bf[j]);
                }
        }
        __syncthreads();
    }

#pragma unroll
    for (int ti = 0; ti < 4; ti++) {
        size_t row0 = (size_t)(m0 + wm * 64 + ti * 16 + r);
#pragma unroll
        for (int j = 0; j < 4; j++) {
            int col = n0 + wn * 32 + j * 8 + 2 * tg;
            if (SPLIT_OUT) {
                float sc = (col < N_EMBD) ? 0.125f : 1.0f;   // pre-scale Q block
                uint32_t hu, lu;
                split2h(acc[ti][j][0] * sc, acc[ti][j][1] * sc, hu, lu);
                *reinterpret_cast<uint32_t*>(Ch + row0 * N + col) = hu;
                *reinterpret_cast<uint32_t*>(Cl + row0 * N + col) = lu;
                split2h(acc[ti][j][2] * sc, acc[ti][j][3] * sc, hu, lu);
                *reinterpret_cast<uint32_t*>(Ch + (row0 + 8) * N + col) = hu;
                *reinterpret_cast<uint32_t*>(Cl + (row0 + 8) * N + col) = lu;
            } else {
                *reinterpret_cast<float2*>(Cf + row0 * N + col) =
                    make_float2(acc[ti][j][0], acc[ti][j][1]);
                *reinterpret_cast<float2*>(Cf + (row0 + 8) * N + col) =
                    make_float2(acc[ti][j][2], acc[ti][j][3]);
            }
        }
    }
}

// ---------------- causal flash attention (cp.async double-buffered K/V) ----------------
// smem bytes (row stride 144): Qh 0, Ql 9216, buf{0,1}: Kh/Vh/Vl 3x9216 each,
// Ph 73728, pmax 82944, psum 83456 -> 83968 total
#define AQH 0
#define AQL 9216
#define ABUF0 18432
#define ABUFSZ 27648
#define APH 73728
#define APMAX 82944
#define APSUM 83456
#define ATT_SMEM_BYTES 83968

__global__ __launch_bounds__(256) void attn_h3(const __half* __restrict__ qkvh,
                                               const __half* __restrict__ qkvl,
                                               __half* __restrict__ atth,
                                               __half* __restrict__ attl)
{
    extern __shared__ char smc[];
    uint32_t (*Ph)[36] = (uint32_t(*)[36])(smc + APH);
    float* pmax = (float*)(smc + APMAX);
    float* psum = (float*)(smc + APSUM);

    const int tid  = threadIdx.x;
    const int wid  = tid >> 5, lane = tid & 31;
    const int wm   = wid & 3,  wn   = wid >> 2;
    const int r    = lane >> 2, tg  = lane & 3;
    const int qt   = (int)gridDim.x - 1 - (int)blockIdx.x;   // big tiles first
    const int bh_  = blockIdx.y;
    const int b    = bh_ >> 4, h = bh_ & 15;
    const uint32_t sbase = (uint32_t)__cvta_generic_to_shared(smc);

    const int srow = tid >> 2;          // 0..63
    const int sch  = (tid & 3) * 2;     // chunk pairs 0,2,4,6

    auto issue_kv = [&](int kt) {
        const uint32_t dbase = sbase + ABUF0 + (uint32_t)(kt & 1) * ABUFSZ;
        size_t rg = (size_t)(b * TT + kt * 64 + srow) * C3 + h * DKH;
        const __half* ks  = qkvh + rg + N_EMBD;
        const __half* vhs = qkvh + rg + 2 * N_EMBD;
        const __half* vls = qkvl + rg + 2 * N_EMBD;
        uint32_t d = dbase + (uint32_t)(srow * 144 + sch * 16);
        cp16(d,                ks  + sch * 8);
        cp16(d + 16,           ks  + sch * 8 + 8);
        cp16(d + 9216,         vhs + sch * 8);
        cp16(d + 9216 + 16,    vhs + sch * 8 + 8);
        cp16(d + 18432,        vls + sch * 8);
        cp16(d + 18432 + 16,   vls + sch * 8 + 8);
    };

    // prologue: stage Q + first K/V tile
    {
        size_t rg = (size_t)(b * TT + qt * 64 + srow) * C3 + h * DKH;
        uint32_t d = sbase + (uint32_t)(srow * 144 + sch * 16);
        cp16(d,               qkvh + rg + sch * 8);
        cp16(d + 16,          qkvh + rg + sch * 8 + 8);
        cp16(d + AQL,         qkvl + rg + sch * 8);
        cp16(d + AQL + 16,    qkvl + rg + sch * 8 + 8);
    }
    issue_kv(0);
    CP_COMMIT();
    CP_WAIT(0);
    __syncthreads();

    // hoist Q fragments into registers (whole kernel)
    const int arow = (lane & 15);
    const int acol = ((lane >> 4) & 1) * 8;
    uint32_t qhf[4][4], qlf[4][4];
#pragma unroll
    for (int s = 0; s < 4; s++) {
        uint32_t ad = sbase + AQH +
            (uint32_t)((wm * 16 + arow) * 144 + (s * 16 + acol) * 2);
        ldsm_x4(qhf[s], ad);
        ldsm_x4(qlf[s], ad + AQL);
    }

    const int mr = wm * 16 + r;
    const int brow_off = ((lane >> 4) & 1) * 8 + (lane & 7);
    const int bcol = ((lane >> 3) & 1) * 8;
    float m0_ = -1e30f, m1_ = -1e30f, l0_ = 0.f, l1_ = 0.f;
    float oacc[4][4] = {};

    for (int kt = 0; kt <= qt; kt++) {
        if (kt < qt) {
            issue_kv(kt + 1);
            CP_COMMIT();
            CP_WAIT(1);
        } else {
            CP_WAIT(0);
        }
        __syncthreads();   // B1: tile kt ready

        const uint32_t kb_base = sbase + ABUF0 + (uint32_t)(kt & 1) * ABUFSZ;
        const uint32_t vh_base = kb_base + 9216u;
        const uint32_t vl_base = kb_base + 18432u;

        // S = Q K^T  (Q split 2-term, K single fp16; K via ldsm)
        float sacc[4][4] = {};
#pragma unroll
        for (int s = 0; s < 4; s++) {
            uint32_t bf[4][2];
#pragma unroll
            for (int g = 0; g < 2; g++) {
                uint32_t bd = kb_base +
                    (uint32_t)((wn * 32 + g * 16 + brow_off) * 144 + (s * 16 + bcol) * 2);
                uint32_t d[4];
                ldsm_x4(d, bd);
                bf[2 * g][0] = d[0]; bf[2 * g][1] = d[1];
                bf[2 * g + 1][0] = d[2]; bf[2 * g + 1][1] = d[3];
            }
#pragma unroll
            for (int j = 0; j < 4; j++) {
                mma_fp16(sacc[j], qhf[s], bf[j]);
                mma_fp16(sacc[j], qlf[s], bf[j]);
            }
        }

        // mask + per-row max (warp partial)
        const int mg0 = qt * 64 + mr;
        float mx0 = -1e30f, mx1 = -1e30f;
#pragma unroll
        for (int j = 0; j < 4; j++) {
            int ng = kt * 64 + wn * 32 + j * 8 + 2 * tg;
            if (ng     > mg0)     sacc[j][0] = -1e30f;
            if (ng + 1 > mg0)     sacc[j][1] = -1e30f;
            if (ng     > mg0 + 8) sacc[j][2] = -1e30f;
            if (ng + 1 > mg0 + 8) sacc[j][3] = -1e30f;
            mx0 = fmaxf(mx0, fmaxf(sacc[j][0], sacc[j][1]));
            mx1 = fmaxf(mx1, fmaxf(sacc[j][2], sacc[j][3]));
        }
        mx0 = fmaxf(mx0, __shfl_xor_sync(0xffffffffu, mx0, 1));
        mx0 = fmaxf(mx0, __shfl_xor_sync(0xffffffffu, mx0, 2));
        mx1 = fmaxf(mx1, __shfl_xor_sync(0xffffffffu, mx1, 1));
        mx1 = fmaxf(mx1, __shfl_xor_sync(0xffffffffu, mx1, 2));
        if (tg == 0) {
            pmax[wn * 64 + mr]     = mx0;
            pmax[wn * 64 + mr + 8] = mx1;
        }
        __syncthreads();   // B2

        float mn0 = fmaxf(m0_, fmaxf(pmax[mr],     pmax[64 + mr]));
        float mn1 = fmaxf(m1_, fmaxf(pmax[mr + 8], pmax[64 + mr + 8]));
        float cr0 = __expf(m0_ - mn0), cr1 = __expf(m1_ - mn1);
        m0_ = mn0; m1_ = mn1;
        float s0 = 0.f, s1 = 0.f;
#pragma unroll
        for (int j = 0; j < 4; j++) {
            float p0 = __expf(sacc[j][0] - mn0), p1 = __expf(sacc[j][1] - mn0);
            float p2 = __expf(sacc[j][2] - mn1), p3 = __expf(sacc[j][3] - mn1);
            s0 += p0 + p1; s1 += p2 + p3;
            int ci = wn * 16 + j * 4 + tg;
            Ph[mr][ci]     = round2h(p0, p1);
            Ph[mr + 8][ci] = round2h(p2, p3);
        }
        s0 += __shfl_xor_sync(0xffffffffu, s0, 1);
        s0 += __shfl_xor_sync(0xffffffffu, s0, 2);
        s1 += __shfl_xor_sync(0xffffffffu, s1, 1);
        s1 += __shfl_xor_sync(0xffffffffu, s1, 2);
        if (tg == 0) {
            psum[wn * 64 + mr]     = s0;
            psum[wn * 64 + mr + 8] = s1;
        }
        __syncthreads();   // B3

        l0_ = l0_ * cr0 + psum[mr]     + psum[64 + mr];
        l1_ = l1_ * cr1 + psum[mr + 8] + psum[64 + mr + 8];
#pragma unroll
        for (int j = 0; j < 4; j++) {
            oacc[j][0] *= cr0; oacc[j][1] *= cr0;
            oacc[j][2] *= cr1; oacc[j][3] *= cr1;
        }

        // O += P @ V (P single fp16, V split; V via ldmatrix.trans)
#pragma unroll
        for (int kb = 0; kb < 32; kb += 8) {
            uint32_t pah[4];
            pah[0] = Ph[mr][kb + tg];
            pah[1] = Ph[mr + 8][kb + tg];
            pah[2] = Ph[mr][kb + tg + 4];
            pah[3] = Ph[mr + 8][kb + tg + 4];
            int krow = kb * 2 + (lane & 15);
#pragma unroll
            for (int j = 0; j < 4; j++) {
                int c0j = wn * 32 + j * 8;
                uint32_t vh0, vh1, vl0, vl1;
                ldm_x2_t(vh0, vh1, vh_base + (uint32_t)(krow * 144 + c0j * 2));
                ldm_x2_t(vl0, vl1, vl_base + (uint32_t)(krow * 144 + c0j * 2));
                uint32_t bhf[2] = { vh0, vh1 };
                uint32_t blf[2] = { vl0, vl1 };
                mma_fp16(oacc[j], pah, bhf);
                mma_fp16(oacc[j], pah, blf);
            }
        }
        __syncthreads();   // B4: buffer reads done before next issue overwrites
    }

    // epilogue: normalize, split to fp16 hi/lo, store
    {
        float inv0 = 1.f / l0_, inv1 = 1.f / l1_;
        size_t row0 = (size_t)(b * TT + qt * 64 + mr);
#pragma unroll
        for (int j = 0; j < 4; j++) {
            int col = h * DKH + wn * 32 + j * 8 + 2 * tg;
            uint32_t hu, lu;
            split2h(oacc[j][0] * inv0, oacc[j][1] * inv0, hu, lu);
            *reinterpret_cast<uint32_t*>(atth + row0 * N_EMBD + col) = hu;
            *reinterpret_cast<uint32_t*>(attl + row0 * N_EMBD + col) = lu;
            split2h(oacc[j][2] * inv1, oacc[j][3] * inv1, hu, lu);
            *reinterpret_cast<uint32_t*>(atth + (row0 + 8) * N_EMBD + col) = hu;
            *reinterpret_cast<uint32_t*>(attl + (row0 + 8) * N_EMBD + col) = lu;
        }
    }
}

// ---------------- launch ----------------
extern "C" void kernel_launch(void* const* d_in, const int* in_sizes, int n_in,
                              void* d_out, int out_size)
{
    const float* x  = (const float*)d_in[0];   // [2,2048,1024]
    const float* wa = (const float*)d_in[1];   // [3072,1024]
    const float* wp = (const float*)d_in[2];   // [1024,1024]
    float* out = (float*)d_out;                // [2,2048,1024]

    __half *xh, *xl, *wah, *wph, *qkvh, *qkvl, *atth, *attl;
    cudaGetSymbolAddress((void**)&xh, g_xh);
    cudaGetSymbolAddress((void**)&xl, g_xl);
    cudaGetSymbolAddress((void**)&wah, g_wah);
    cudaGetSymbolAddress((void**)&wph, g_wph);
    cudaGetSymbolAddress((void**)&qkvh, g_qkvh);
    cudaGetSymbolAddress((void**)&qkvl, g_qkvl);
    cudaGetSymbolAddress((void**)&atth, g_atth);
    cudaGetSymbolAddress((void**)&attl, g_attl);

    cudaFuncSetAttribute(gemm_h_pipe<true>,
                         cudaFuncAttributeMaxDynamicSharedMemorySize, GEMM_SMEM);
    cudaFuncSetAttribute(gemm_h_pipe<false>,
                         cudaFuncAttributeMaxDynamicSharedMemorySize, GEMM_SMEM);
    cudaFuncSetAttribute(attn_h3,
                         cudaFuncAttributeMaxDynamicSharedMemorySize, ATT_SMEM_BYTES);

    // 0) precision prep
    conv_split<<<BT * N_EMBD / 1024, 256>>>(x, xh, xl);
    conv_round<<<C3 * N_EMBD / 1024, 256>>>(wa, wah);
    conv_round<<<N_EMBD * N_EMBD / 1024, 256>>>(wp, wph);

    // 1) fused QKV projection -> split fp16 (Q pre-scaled by 0.125)
    gemm_h_pipe<true><<<dim3(C3 / 128, BT / 128), 256, GEMM_SMEM>>>(
        xh, xl, wah, nullptr, qkvh, qkvl, BT, C3, N_EMBD);

    // 2) causal attention (pure fp16 cp.async staging)
    attn_h3<<<dim3(TT / 64, BB * N_HEAD), 256, ATT_SMEM_BYTES>>>(qkvh, qkvl, atth, attl);

    // 3) output projection -> fp32 out
    gemm_h_pipe<false><<<dim3(N_EMBD / 128, BT / 128), 256, GEMM_SMEM>>>(
        atth, attl, wph, out, nullptr, nullptr, BT, N_EMBD, N_EMBD);
}